// round 1
// baseline (speedup 1.0000x reference)
#include <cuda_runtime.h>
#include <cstdint>
#include <cstddef>

#define L      2048
#define NE     768
#define DI     1536
#define DS     16
#define DTR    48
#define XDBLW  80
#define NCHUNK 64
#define CH     32   // NCHUNK*CH == L

// ---------------- scratch (static device globals; no allocation) ----------------
__device__ float g_h[L * NE];
__device__ float g_xn[L * NE];
__device__ float g_xr[L * 2 * DI];
__device__ float g_xc[L * DI];
__device__ float g_xdbl[L * XDBLW];
__device__ float g_delta[L * DI];
__device__ float g_y[L * DI];
__device__ float g_fin[NCHUNK * DI * DS];
__device__ float g_prod[NCHUNK * DI * DS];
__device__ float g_init[NCHUNK * DI * DS];

// ---------------- small helpers ----------------
__device__ __forceinline__ float sigmoid_mul(float x) {            // silu
    return x / (1.f + __expf(-x));
}

// ---------------- embedding ----------------
__global__ void embed_kernel(const int* __restrict__ tok, const float* __restrict__ E,
                             float* __restrict__ h) {
    int i = blockIdx.x * 256 + threadIdx.x;
    if (i < L * NE) {
        int t = i / NE, e = i - t * NE;
        h[i] = E[(size_t)tok[t] * NE + e];
    }
}

// ---------------- rmsnorm ----------------
__global__ void rmsnorm_kernel(const float* __restrict__ in, const float* __restrict__ w,
                               const float* __restrict__ b, float* __restrict__ out) {
    int t = blockIdx.x;
    const float* row = in + (size_t)t * NE;
    float s = 0.f;
    for (int i = threadIdx.x; i < NE; i += 256) { float v = row[i]; s += v * v; }
    __shared__ float red[256];
    red[threadIdx.x] = s;
    __syncthreads();
    for (int st = 128; st > 0; st >>= 1) {
        if (threadIdx.x < st) red[threadIdx.x] += red[threadIdx.x + st];
        __syncthreads();
    }
    float inv = rsqrtf(red[0] / (float)NE + 1e-5f);
    for (int i = threadIdx.x; i < NE; i += 256)
        out[(size_t)t * NE + i] = row[i] * inv * w[i] + b[i];
}

// ---------------- generic fp32 GEMM:  C[M,N] = A[M,K] @ B[N,K]^T (+bias/softplus/residual)
__global__ __launch_bounds__(256, 2) void gemm_nt(
    const float* __restrict__ A, int lda,
    const float* __restrict__ B, int ldb,
    float* __restrict__ C, int ldc,
    const float* __restrict__ Res,
    const float* __restrict__ bias,
    int M, int N, int K, int act) {
    __shared__ float As[8][128];
    __shared__ float Bs[8][128];
    int bm = blockIdx.y * 128;
    int bn = blockIdx.x * 128;
    int tid = threadIdx.x;
    int tx = tid & 15;         // 16 cols of 8
    int ty = tid >> 4;         // 16 rows of 8
    int lrow = tid >> 1;       // 0..127
    int lcol = (tid & 1) << 2; // 0 or 4

    float acc[8][8];
#pragma unroll
    for (int i = 0; i < 8; i++)
#pragma unroll
        for (int j = 0; j < 8; j++) acc[i][j] = 0.f;

    const float* Ap = A + (size_t)(bm + lrow) * lda + lcol;
    const float* Bp = B + (size_t)(bn + lrow) * ldb + lcol;
    bool aok = (bm + lrow) < M;
    bool bok = (bn + lrow) < N;

    for (int k0 = 0; k0 < K; k0 += 8) {
        float4 av = make_float4(0.f, 0.f, 0.f, 0.f);
        float4 bv = make_float4(0.f, 0.f, 0.f, 0.f);
        if (aok) av = *(const float4*)(Ap + k0);
        if (bok) bv = *(const float4*)(Bp + k0);
        As[lcol + 0][lrow] = av.x; As[lcol + 1][lrow] = av.y;
        As[lcol + 2][lrow] = av.z; As[lcol + 3][lrow] = av.w;
        Bs[lcol + 0][lrow] = bv.x; Bs[lcol + 1][lrow] = bv.y;
        Bs[lcol + 2][lrow] = bv.z; Bs[lcol + 3][lrow] = bv.w;
        __syncthreads();
#pragma unroll
        for (int kk = 0; kk < 8; kk++) {
            float a[8], b[8];
            *(float4*)&a[0] = *(const float4*)&As[kk][ty * 8];
            *(float4*)&a[4] = *(const float4*)&As[kk][ty * 8 + 4];
            *(float4*)&b[0] = *(const float4*)&Bs[kk][tx * 8];
            *(float4*)&b[4] = *(const float4*)&Bs[kk][tx * 8 + 4];
#pragma unroll
            for (int i = 0; i < 8; i++)
#pragma unroll
                for (int j = 0; j < 8; j++)
                    acc[i][j] = fmaf(a[i], b[j], acc[i][j]);
        }
        __syncthreads();
    }
#pragma unroll
    for (int i = 0; i < 8; i++) {
        int row = bm + ty * 8 + i;
        if (row >= M) continue;
#pragma unroll
        for (int j = 0; j < 8; j++) {
            int col = bn + tx * 8 + j;
            if (col >= N) continue;
            float v = acc[i][j];
            if (bias) v += bias[col];
            if (act) v = fmaxf(v, 0.f) + log1pf(__expf(-fabsf(v)));  // softplus
            if (Res) v += Res[(size_t)row * ldc + col];
            C[(size_t)row * ldc + col] = v;
        }
    }
}

// ---------------- depthwise causal conv (d_conv=4) + bias + silu ----------------
__global__ void conv_silu_kernel(const float* __restrict__ xr, const float* __restrict__ cw,
                                 const float* __restrict__ cb, float* __restrict__ xc) {
    int i = blockIdx.x * 256 + threadIdx.x;
    if (i >= L * DI) return;
    int t = i / DI, d = i - t * DI;
    float acc = cb[d];
#pragma unroll
    for (int j = 0; j < 4; j++) {
        int ts = t - 3 + j;
        if (ts >= 0) acc = fmaf(cw[d * 4 + j], xr[(size_t)ts * (2 * DI) + d], acc);
    }
    xc[i] = sigmoid_mul(acc);
}

// ---------------- chunked selective scan ----------------
// phase 1: local scan with zero init; record chunk-final state and decay product
__global__ __launch_bounds__(128) void scan_phase1(
    const float* __restrict__ delta, const float* __restrict__ u,
    const float* __restrict__ xdbl, const float* __restrict__ A_log,
    float* __restrict__ fin, float* __restrict__ prod) {
    int p = blockIdx.y;
    int d = blockIdx.x * 128 + threadIdx.x;
    __shared__ float Bs[CH][DS];
    for (int i = threadIdx.x; i < CH * DS; i += 128) {
        int tt = i >> 4, n = i & 15;
        Bs[tt][n] = xdbl[(size_t)(p * CH + tt) * XDBLW + DTR + n];
    }
    __syncthreads();
    float Aa[DS], x[DS], pa[DS];
#pragma unroll
    for (int n = 0; n < DS; n++) {
        Aa[n] = -__expf(A_log[(size_t)d * DS + n]);
        x[n] = 0.f;
        pa[n] = 1.f;
    }
    for (int tt = 0; tt < CH; tt++) {
        int t = p * CH + tt;
        float dl = delta[(size_t)t * DI + d];
        float uu = u[(size_t)t * DI + d];
        float du = dl * uu;
#pragma unroll
        for (int n = 0; n < DS; n++) {
            float e = __expf(dl * Aa[n]);
            x[n] = fmaf(e, x[n], du * Bs[tt][n]);
            pa[n] *= e;
        }
    }
    size_t base = (size_t)p * DI * DS + (size_t)d * DS;
#pragma unroll
    for (int n = 0; n < DS; n++) { fin[base + n] = x[n]; prod[base + n] = pa[n]; }
}

// sequential combine across chunks (per (d,n) pair)
__global__ void scan_combine(const float* __restrict__ fin, const float* __restrict__ prod,
                             float* __restrict__ init) {
    int i = blockIdx.x * 256 + threadIdx.x;
    if (i >= DI * DS) return;
    float s = 0.f;
#pragma unroll 4
    for (int p = 0; p < NCHUNK; p++) {
        size_t idx = (size_t)p * DI * DS + i;
        init[idx] = s;
        s = fmaf(prod[idx], s, fin[idx]);
    }
}

// phase 2: rescan with true init, emit y = (scan + u*D) * silu(res)
__global__ __launch_bounds__(128) void scan_phase2(
    const float* __restrict__ delta, const float* __restrict__ u,
    const float* __restrict__ xdbl, const float* __restrict__ A_log,
    const float* __restrict__ init, const float* __restrict__ Dp,
    const float* __restrict__ xr, float* __restrict__ yout) {
    int p = blockIdx.y;
    int d = blockIdx.x * 128 + threadIdx.x;
    __shared__ float Bs[CH][DS];
    __shared__ float Cs[CH][DS];
    for (int i = threadIdx.x; i < CH * DS; i += 128) {
        int tt = i >> 4, n = i & 15;
        size_t row = (size_t)(p * CH + tt) * XDBLW;
        Bs[tt][n] = xdbl[row + DTR + n];
        Cs[tt][n] = xdbl[row + DTR + DS + n];
    }
    __syncthreads();
    float Aa[DS], x[DS];
    size_t base = (size_t)p * DI * DS + (size_t)d * DS;
#pragma unroll
    for (int n = 0; n < DS; n++) {
        Aa[n] = -__expf(A_log[(size_t)d * DS + n]);
        x[n] = init[base + n];
    }
    float Dd = Dp[d];
    for (int tt = 0; tt < CH; tt++) {
        int t = p * CH + tt;
        float dl = delta[(size_t)t * DI + d];
        float uu = u[(size_t)t * DI + d];
        float du = dl * uu;
        float y0 = 0.f, y1 = 0.f, y2 = 0.f, y3 = 0.f;
#pragma unroll
        for (int n = 0; n < DS; n++) {
            float e = __expf(dl * Aa[n]);
            x[n] = fmaf(e, x[n], du * Bs[tt][n]);
            float pr = x[n] * Cs[tt][n];
            if ((n & 3) == 0) y0 += pr;
            else if ((n & 3) == 1) y1 += pr;
            else if ((n & 3) == 2) y2 += pr;
            else y3 += pr;
        }
        float y = (y0 + y1) + (y2 + y3) + uu * Dd;
        float r = xr[(size_t)t * (2 * DI) + DI + d];
        yout[(size_t)t * DI + d] = y * sigmoid_mul(r);
    }
}

// ---------------- host orchestration ----------------
static void launch_gemm(const float* A, int lda, const float* B, int ldb,
                        float* C, int ldc, const float* Res, const float* bias,
                        int M, int N, int K, int act) {
    dim3 grid((N + 127) / 128, (M + 127) / 128);
    gemm_nt<<<grid, 256>>>(A, lda, B, ldb, C, ldc, Res, bias, M, N, K, act);
}

extern "C" void kernel_launch(void* const* d_in, const int* in_sizes, int n_in,
                              void* d_out, int out_size) {
    const int*   tokens = (const int*)d_in[0];
    const float* E      = (const float*)d_in[1];
    const float* in_w   = (const float*)d_in[2];
    const float* conv_w = (const float*)d_in[3];
    const float* conv_b = (const float*)d_in[4];
    const float* xp_w   = (const float*)d_in[5];
    const float* dt_w   = (const float*)d_in[6];
    const float* dt_b   = (const float*)d_in[7];
    const float* A_log  = (const float*)d_in[8];
    const float* Dp     = (const float*)d_in[9];
    const float* out_w  = (const float*)d_in[10];
    const float* nw     = (const float*)d_in[11];
    const float* nb     = (const float*)d_in[12];
    const float* nfw    = (const float*)d_in[13];
    const float* nfb    = (const float*)d_in[14];
    float* logits = (float*)d_out;

    float *h, *xn, *xr, *xc, *xdbl, *delta, *y, *fin, *prod, *init;
    cudaGetSymbolAddress((void**)&h, g_h);
    cudaGetSymbolAddress((void**)&xn, g_xn);
    cudaGetSymbolAddress((void**)&xr, g_xr);
    cudaGetSymbolAddress((void**)&xc, g_xc);
    cudaGetSymbolAddress((void**)&xdbl, g_xdbl);
    cudaGetSymbolAddress((void**)&delta, g_delta);
    cudaGetSymbolAddress((void**)&y, g_y);
    cudaGetSymbolAddress((void**)&fin, g_fin);
    cudaGetSymbolAddress((void**)&prod, g_prod);
    cudaGetSymbolAddress((void**)&init, g_init);

    embed_kernel<<<(L * NE + 255) / 256, 256>>>(tokens, E, h);

    for (int l = 0; l < 2; l++) {
        const float* l_inw  = in_w  + (size_t)l * (2 * DI) * NE;
        const float* l_cw   = conv_w + (size_t)l * DI * 4;
        const float* l_cb   = conv_b + (size_t)l * DI;
        const float* l_xpw  = xp_w  + (size_t)l * XDBLW * DI;
        const float* l_dtw  = dt_w  + (size_t)l * DI * DTR;
        const float* l_dtb  = dt_b  + (size_t)l * DI;
        const float* l_alog = A_log + (size_t)l * DI * DS;
        const float* l_dp   = Dp    + (size_t)l * DI;
        const float* l_outw = out_w + (size_t)l * NE * DI;

        // xn = rmsnorm(h)
        rmsnorm_kernel<<<L, 256>>>(h, nw + l * NE, nb + l * NE, xn);
        // xr = xn @ in_proj^T   [L, 2*DI]
        launch_gemm(xn, NE, l_inw, NE, xr, 2 * DI, nullptr, nullptr, L, 2 * DI, NE, 0);
        // xc = silu(depthwise causal conv(x) + b)
        conv_silu_kernel<<<(L * DI + 255) / 256, 256>>>(xr, l_cw, l_cb, xc);
        // xdbl = xc @ x_proj^T  [L, 80]
        launch_gemm(xc, DI, l_xpw, DI, xdbl, XDBLW, nullptr, nullptr, L, XDBLW, DI, 0);
        // delta = softplus(xdbl[:, :48] @ dt_proj^T + dt_b)  [L, DI]
        launch_gemm(xdbl, XDBLW, l_dtw, DTR, delta, DI, nullptr, l_dtb, L, DI, DTR, 1);
        // chunked selective scan -> y (fused +u*D and *silu(res))
        scan_phase1<<<dim3(DI / 128, NCHUNK), 128>>>(delta, xc, xdbl, l_alog, fin, prod);
        scan_combine<<<(DI * DS + 255) / 256, 256>>>(fin, prod, init);
        scan_phase2<<<dim3(DI / 128, NCHUNK), 128>>>(delta, xc, xdbl, l_alog, init, l_dp, xr, y);
        // h = h + y @ out_proj^T
        launch_gemm(y, DI, l_outw, DI, h, NE, h, nullptr, L, NE, DI, 0);
    }

    // final norm + tied lm head
    rmsnorm_kernel<<<L, 256>>>(h, nfw, nfb, xn);
    launch_gemm(xn, NE, E, NE, logits, 32000, nullptr, nullptr, L, 32000, NE, 0);
}

// round 3
// speedup vs baseline: 2.5564x; 2.5564x over previous
#include <cuda_runtime.h>
#include <cuda_bf16.h>
#include <cstdint>
#include <cstddef>

#define L      2048
#define NE     768
#define DI     1536
#define DS     16
#define DTR    48
#define XDBLW  80
#define NCHUNK 64
#define CH     32   // NCHUNK*CH == L

// ---------------- scratch (static device globals; no allocation) ----------------
__device__ float g_h[L * NE];
__device__ float g_xn[L * NE];
__device__ float g_xr[L * 2 * DI];
__device__ float g_xc[L * DI];
__device__ float g_xdbl[L * XDBLW];
__device__ float g_delta[L * DI];
__device__ float g_y[L * DI];
__device__ float g_fin[NCHUNK * DI * DS];
__device__ float g_prod[NCHUNK * DI * DS];
__device__ float g_init[NCHUNK * DI * DS];

// ---------------- helpers ----------------
__device__ __forceinline__ uint32_t smem_u32(const void* p) {
    uint32_t a;
    asm("{ .reg .u64 t; cvta.to.shared.u64 t, %1; cvt.u32.u64 %0, t; }" : "=r"(a) : "l"(p));
    return a;
}
__device__ __forceinline__ void cp16(uint32_t s, const void* g) {
    asm volatile("cp.async.cg.shared.global [%0], [%1], 16;" :: "r"(s), "l"(g));
}
__device__ __forceinline__ void cp_commit() {
    asm volatile("cp.async.commit_group;" ::: "memory");
}
__device__ __forceinline__ uint32_t f2tf(float x) {
    uint32_t r;
    asm("cvt.rna.tf32.f32 %0, %1;" : "=r"(r) : "f"(x));
    return r;
}
__device__ __forceinline__ float sigmoid_mul(float x) { return x / (1.f + __expf(-x)); }

// ---------------- embedding ----------------
__global__ void embed_kernel(const int* __restrict__ tok, const float* __restrict__ E,
                             float* __restrict__ h) {
    int i = blockIdx.x * 256 + threadIdx.x;
    if (i < L * NE) {
        int t = i / NE, e = i - t * NE;
        h[i] = E[(size_t)tok[t] * NE + e];
    }
}

// ---------------- rmsnorm ----------------
__global__ void rmsnorm_kernel(const float* __restrict__ in, const float* __restrict__ w,
                               const float* __restrict__ b, float* __restrict__ out) {
    int t = blockIdx.x;
    const float* row = in + (size_t)t * NE;
    float s = 0.f;
    for (int i = threadIdx.x; i < NE; i += 256) { float v = row[i]; s += v * v; }
    __shared__ float red[256];
    red[threadIdx.x] = s;
    __syncthreads();
    for (int st = 128; st > 0; st >>= 1) {
        if (threadIdx.x < st) red[threadIdx.x] += red[threadIdx.x + st];
        __syncthreads();
    }
    float inv = rsqrtf(red[0] / (float)NE + 1e-5f);
    for (int i = threadIdx.x; i < NE; i += 256)
        out[(size_t)t * NE + i] = row[i] * inv * w[i] + b[i];
}

// ======================================================================================
// Tensor-core tf32 GEMM via mma.sync (works on baseline compute_103 PTX):
//   C[M,N] = A[M,K] @ B[N,K]^T (+Res)
// CTA tile 128x128, 8 warps of 64x32, BK=32, double-buffered cp.async staging.
// Requires M%128==0, N%128==0, K%32==0.
// smem rows padded to 36 floats: fragment LDS banks = 4r+c -> conflict-free.
// ======================================================================================
#define TCSM (2 * 128 * 36)           // floats per operand (2 buffers)
#define TCSMEM_BYTES (2 * TCSM * 4)   // 73728 bytes total

__global__ __launch_bounds__(256, 1) void gemm_mma(
    const float* __restrict__ A, const float* __restrict__ B,
    float* __restrict__ C, const float* __restrict__ Res,
    int M, int N, int K) {
    extern __shared__ float smem[];
    float* As = smem;            // [2][128][36]
    float* Bs = smem + TCSM;     // [2][128][36]

    const int tid = threadIdx.x, wid = tid >> 5, lane = tid & 31;
    const int wm = wid >> 2, wn = wid & 3;          // warp grid 2 x 4
    const int bm = blockIdx.x * 128, bn = blockIdx.y * 128;
    const int NC = K >> 5;
    const int r = lane >> 2, cq = lane & 3;

    float acc[4][4][4];
#pragma unroll
    for (int i = 0; i < 4; i++)
#pragma unroll
        for (int j = 0; j < 4; j++)
#pragma unroll
            for (int q = 0; q < 4; q++) acc[i][j][q] = 0.f;

    const int srow = tid >> 3, scol = (tid & 7) * 4;     // staging: 4 iters cover 128x32

    auto stage = [&](int c, int b) {
        int k0 = c * 32;
        float* sa = As + b * (128 * 36);
        float* sb = Bs + b * (128 * 36);
#pragma unroll
        for (int i = 0; i < 4; i++) {
            int rr = srow + i * 32;
            cp16(smem_u32(sa + rr * 36 + scol), A + (size_t)(bm + rr) * K + k0 + scol);
            cp16(smem_u32(sb + rr * 36 + scol), B + (size_t)(bn + rr) * K + k0 + scol);
        }
        cp_commit();
    };

    stage(0, 0);
    for (int c = 0; c < NC; c++) {
        int buf = c & 1;
        if (c + 1 < NC) {
            stage(c + 1, buf ^ 1);
            asm volatile("cp.async.wait_group 1;" ::: "memory");
        } else {
            asm volatile("cp.async.wait_group 0;" ::: "memory");
        }
        __syncthreads();

        const float* sa = As + buf * (128 * 36) + (wm * 64 + r) * 36;
        const float* sb = Bs + buf * (128 * 36) + (wn * 32 + r) * 36;
#pragma unroll
        for (int ks = 0; ks < 4; ks++) {
            int k = ks * 8 + cq;
            uint32_t af[4][4];
#pragma unroll
            for (int i = 0; i < 4; i++) {
                const float* p = sa + i * 16 * 36 + k;
                af[i][0] = f2tf(p[0]);
                af[i][1] = f2tf(p[8 * 36]);
                af[i][2] = f2tf(p[4]);
                af[i][3] = f2tf(p[8 * 36 + 4]);
            }
            uint32_t bf[4][2];
#pragma unroll
            for (int j = 0; j < 4; j++) {
                const float* p = sb + j * 8 * 36 + k;
                bf[j][0] = f2tf(p[0]);
                bf[j][1] = f2tf(p[4]);
            }
#pragma unroll
            for (int i = 0; i < 4; i++)
#pragma unroll
                for (int j = 0; j < 4; j++)
                    asm volatile(
                        "mma.sync.aligned.m16n8k8.row.col.f32.tf32.tf32.f32 "
                        "{%0,%1,%2,%3}, {%4,%5,%6,%7}, {%8,%9}, {%0,%1,%2,%3};"
                        : "+f"(acc[i][j][0]), "+f"(acc[i][j][1]),
                          "+f"(acc[i][j][2]), "+f"(acc[i][j][3])
                        : "r"(af[i][0]), "r"(af[i][1]), "r"(af[i][2]), "r"(af[i][3]),
                          "r"(bf[j][0]), "r"(bf[j][1]));
        }
        __syncthreads();
    }

    // epilogue
#pragma unroll
    for (int i = 0; i < 4; i++) {
        int r0 = bm + wm * 64 + i * 16 + r;
#pragma unroll
        for (int j = 0; j < 4; j++) {
            int c0 = bn + wn * 32 + j * 8 + cq * 2;
            float2 v0 = make_float2(acc[i][j][0], acc[i][j][1]);
            float2 v1 = make_float2(acc[i][j][2], acc[i][j][3]);
            if (Res) {
                float2 p0 = *(const float2*)&Res[(size_t)r0 * N + c0];
                float2 p1 = *(const float2*)&Res[(size_t)(r0 + 8) * N + c0];
                v0.x += p0.x; v0.y += p0.y;
                v1.x += p1.x; v1.y += p1.y;
            }
            *(float2*)&C[(size_t)r0 * N + c0] = v0;
            *(float2*)&C[(size_t)(r0 + 8) * N + c0] = v1;
        }
    }
}

// ---------------- generic fp32 SIMT GEMM (small shapes): C = A @ B^T (+bias/softplus) ----
__global__ __launch_bounds__(256, 2) void gemm_nt(
    const float* __restrict__ A, int lda,
    const float* __restrict__ B, int ldb,
    float* __restrict__ C, int ldc,
    const float* __restrict__ Res,
    const float* __restrict__ bias,
    int M, int N, int K, int act) {
    __shared__ float As[8][128];
    __shared__ float Bs[8][128];
    int bm = blockIdx.y * 128;
    int bn = blockIdx.x * 128;
    int tid = threadIdx.x;
    int tx = tid & 15;
    int ty = tid >> 4;
    int lrow = tid >> 1;
    int lcol = (tid & 1) << 2;

    float acc[8][8];
#pragma unroll
    for (int i = 0; i < 8; i++)
#pragma unroll
        for (int j = 0; j < 8; j++) acc[i][j] = 0.f;

    const float* Ap = A + (size_t)(bm + lrow) * lda + lcol;
    const float* Bp = B + (size_t)(bn + lrow) * ldb + lcol;
    bool aok = (bm + lrow) < M;
    bool bok = (bn + lrow) < N;

    for (int k0 = 0; k0 < K; k0 += 8) {
        float4 av = make_float4(0.f, 0.f, 0.f, 0.f);
        float4 bv = make_float4(0.f, 0.f, 0.f, 0.f);
        if (aok && k0 + lcol < K) av = *(const float4*)(Ap + k0);
        if (bok && k0 + lcol < K) bv = *(const float4*)(Bp + k0);
        As[lcol + 0][lrow] = av.x; As[lcol + 1][lrow] = av.y;
        As[lcol + 2][lrow] = av.z; As[lcol + 3][lrow] = av.w;
        Bs[lcol + 0][lrow] = bv.x; Bs[lcol + 1][lrow] = bv.y;
        Bs[lcol + 2][lrow] = bv.z; Bs[lcol + 3][lrow] = bv.w;
        __syncthreads();
#pragma unroll
        for (int kk = 0; kk < 8; kk++) {
            float a[8], b[8];
            *(float4*)&a[0] = *(const float4*)&As[kk][ty * 8];
            *(float4*)&a[4] = *(const float4*)&As[kk][ty * 8 + 4];
            *(float4*)&b[0] = *(const float4*)&Bs[kk][tx * 8];
            *(float4*)&b[4] = *(const float4*)&Bs[kk][tx * 8 + 4];
#pragma unroll
            for (int i = 0; i < 8; i++)
#pragma unroll
                for (int j = 0; j < 8; j++)
                    acc[i][j] = fmaf(a[i], b[j], acc[i][j]);
        }
        __syncthreads();
    }
#pragma unroll
    for (int i = 0; i < 8; i++) {
        int row = bm + ty * 8 + i;
        if (row >= M) continue;
#pragma unroll
        for (int j = 0; j < 8; j++) {
            int col = bn + tx * 8 + j;
            if (col >= N) continue;
            float v = acc[i][j];
            if (bias) v += bias[col];
            if (act) v = fmaxf(v, 0.f) + log1pf(__expf(-fabsf(v)));  // softplus
            if (Res) v += Res[(size_t)row * ldc + col];
            C[(size_t)row * ldc + col] = v;
        }
    }
}

// ---------------- depthwise causal conv (d_conv=4) + bias + silu ----------------
__global__ void conv_silu_kernel(const float* __restrict__ xr, const float* __restrict__ cw,
                                 const float* __restrict__ cb, float* __restrict__ xc) {
    int i = blockIdx.x * 256 + threadIdx.x;
    if (i >= L * DI) return;
    int t = i / DI, d = i - t * DI;
    float acc = cb[d];
#pragma unroll
    for (int j = 0; j < 4; j++) {
        int ts = t - 3 + j;
        if (ts >= 0) acc = fmaf(cw[d * 4 + j], xr[(size_t)ts * (2 * DI) + d], acc);
    }
    xc[i] = sigmoid_mul(acc);
}

// ---------------- chunked selective scan ----------------
__global__ __launch_bounds__(128) void scan_phase1(
    const float* __restrict__ delta, const float* __restrict__ u,
    const float* __restrict__ xdbl, const float* __restrict__ A_log,
    float* __restrict__ fin, float* __restrict__ prod) {
    int p = blockIdx.y;
    int d = blockIdx.x * 128 + threadIdx.x;
    __shared__ float Bs[CH][DS];
    for (int i = threadIdx.x; i < CH * DS; i += 128) {
        int tt = i >> 4, n = i & 15;
        Bs[tt][n] = xdbl[(size_t)(p * CH + tt) * XDBLW + DTR + n];
    }
    __syncthreads();
    float Aa[DS], x[DS], pa[DS];
#pragma unroll
    for (int n = 0; n < DS; n++) {
        Aa[n] = -__expf(A_log[(size_t)d * DS + n]);
        x[n] = 0.f;
        pa[n] = 1.f;
    }
    for (int tt = 0; tt < CH; tt++) {
        int t = p * CH + tt;
        float dl = delta[(size_t)t * DI + d];
        float uu = u[(size_t)t * DI + d];
        float du = dl * uu;
#pragma unroll
        for (int n = 0; n < DS; n++) {
            float e = __expf(dl * Aa[n]);
            x[n] = fmaf(e, x[n], du * Bs[tt][n]);
            pa[n] *= e;
        }
    }
    size_t base = (size_t)p * DI * DS + (size_t)d * DS;
#pragma unroll
    for (int n = 0; n < DS; n++) { fin[base + n] = x[n]; prod[base + n] = pa[n]; }
}

__global__ void scan_combine(const float* __restrict__ fin, const float* __restrict__ prod,
                             float* __restrict__ init) {
    int i = blockIdx.x * 256 + threadIdx.x;
    if (i >= DI * DS) return;
    float s = 0.f;
#pragma unroll 4
    for (int p = 0; p < NCHUNK; p++) {
        size_t idx = (size_t)p * DI * DS + i;
        init[idx] = s;
        s = fmaf(prod[idx], s, fin[idx]);
    }
}

__global__ __launch_bounds__(128) void scan_phase2(
    const float* __restrict__ delta, const float* __restrict__ u,
    const float* __restrict__ xdbl, const float* __restrict__ A_log,
    const float* __restrict__ init, const float* __restrict__ Dp,
    const float* __restrict__ xr, float* __restrict__ yout) {
    int p = blockIdx.y;
    int d = blockIdx.x * 128 + threadIdx.x;
    __shared__ float Bs[CH][DS];
    __shared__ float Cs[CH][DS];
    for (int i = threadIdx.x; i < CH * DS; i += 128) {
        int tt = i >> 4, n = i & 15;
        size_t row = (size_t)(p * CH + tt) * XDBLW;
        Bs[tt][n] = xdbl[row + DTR + n];
        Cs[tt][n] = xdbl[row + DTR + DS + n];
    }
    __syncthreads();
    float Aa[DS], x[DS];
    size_t base = (size_t)p * DI * DS + (size_t)d * DS;
#pragma unroll
    for (int n = 0; n < DS; n++) {
        Aa[n] = -__expf(A_log[(size_t)d * DS + n]);
        x[n] = init[base + n];
    }
    float Dd = Dp[d];
    for (int tt = 0; tt < CH; tt++) {
        int t = p * CH + tt;
        float dl = delta[(size_t)t * DI + d];
        float uu = u[(size_t)t * DI + d];
        float du = dl * uu;
        float y0 = 0.f, y1 = 0.f, y2 = 0.f, y3 = 0.f;
#pragma unroll
        for (int n = 0; n < DS; n++) {
            float e = __expf(dl * Aa[n]);
            x[n] = fmaf(e, x[n], du * Bs[tt][n]);
            float pr = x[n] * Cs[tt][n];
            if ((n & 3) == 0) y0 += pr;
            else if ((n & 3) == 1) y1 += pr;
            else if ((n & 3) == 2) y2 += pr;
            else y3 += pr;
        }
        float y = (y0 + y1) + (y2 + y3) + uu * Dd;
        float r = xr[(size_t)t * (2 * DI) + DI + d];
        yout[(size_t)t * DI + d] = y * sigmoid_mul(r);
    }
}

// ---------------- host orchestration ----------------
static void launch_gemm_nt(const float* A, int lda, const float* B, int ldb,
                           float* C, int ldc, const float* Res, const float* bias,
                           int M, int N, int K, int act) {
    dim3 grid((N + 127) / 128, (M + 127) / 128);
    gemm_nt<<<grid, 256>>>(A, lda, B, ldb, C, ldc, Res, bias, M, N, K, act);
}

static void launch_gemm_tf32(const float* A, const float* B, float* C,
                             const float* Res, int M, int N, int K) {
    dim3 grid(M / 128, N / 128);   // M fast -> CTA waves share one B column-panel
    gemm_mma<<<grid, 256, TCSMEM_BYTES>>>(A, B, C, Res, M, N, K);
}

extern "C" void kernel_launch(void* const* d_in, const int* in_sizes, int n_in,
                              void* d_out, int out_size) {
    const int*   tokens = (const int*)d_in[0];
    const float* E      = (const float*)d_in[1];
    const float* in_w   = (const float*)d_in[2];
    const float* conv_w = (const float*)d_in[3];
    const float* conv_b = (const float*)d_in[4];
    const float* xp_w   = (const float*)d_in[5];
    const float* dt_w   = (const float*)d_in[6];
    const float* dt_b   = (const float*)d_in[7];
    const float* A_log  = (const float*)d_in[8];
    const float* Dp     = (const float*)d_in[9];
    const float* out_w  = (const float*)d_in[10];
    const float* nw     = (const float*)d_in[11];
    const float* nb     = (const float*)d_in[12];
    const float* nfw    = (const float*)d_in[13];
    const float* nfb    = (const float*)d_in[14];
    float* logits = (float*)d_out;

    float *h, *xn, *xr, *xc, *xdbl, *delta, *y, *fin, *prod, *init;
    cudaGetSymbolAddress((void**)&h, g_h);
    cudaGetSymbolAddress((void**)&xn, g_xn);
    cudaGetSymbolAddress((void**)&xr, g_xr);
    cudaGetSymbolAddress((void**)&xc, g_xc);
    cudaGetSymbolAddress((void**)&xdbl, g_xdbl);
    cudaGetSymbolAddress((void**)&delta, g_delta);
    cudaGetSymbolAddress((void**)&y, g_y);
    cudaGetSymbolAddress((void**)&fin, g_fin);
    cudaGetSymbolAddress((void**)&prod, g_prod);
    cudaGetSymbolAddress((void**)&init, g_init);

    cudaFuncSetAttribute(gemm_mma, cudaFuncAttributeMaxDynamicSharedMemorySize, TCSMEM_BYTES);

    embed_kernel<<<(L * NE + 255) / 256, 256>>>(tokens, E, h);

    for (int l = 0; l < 2; l++) {
        const float* l_inw  = in_w  + (size_t)l * (2 * DI) * NE;
        const float* l_cw   = conv_w + (size_t)l * DI * 4;
        const float* l_cb   = conv_b + (size_t)l * DI;
        const float* l_xpw  = xp_w  + (size_t)l * XDBLW * DI;
        const float* l_dtw  = dt_w  + (size_t)l * DI * DTR;
        const float* l_dtb  = dt_b  + (size_t)l * DI;
        const float* l_alog = A_log + (size_t)l * DI * DS;
        const float* l_dp   = Dp    + (size_t)l * DI;
        const float* l_outw = out_w + (size_t)l * NE * DI;

        // xn = rmsnorm(h)
        rmsnorm_kernel<<<L, 256>>>(h, nw + l * NE, nb + l * NE, xn);
        // xr = xn @ in_proj^T  [L, 2*DI]   (tensor core tf32)
        launch_gemm_tf32(xn, l_inw, xr, nullptr, L, 2 * DI, NE);
        // xc = silu(depthwise causal conv(x) + b)
        conv_silu_kernel<<<(L * DI + 255) / 256, 256>>>(xr, l_cw, l_cb, xc);
        // xdbl = xc @ x_proj^T  [L, 80]  (SIMT, small N)
        launch_gemm_nt(xc, DI, l_xpw, DI, xdbl, XDBLW, nullptr, nullptr, L, XDBLW, DI, 0);
        // delta = softplus(xdbl[:, :48] @ dt_proj^T + dt_b)  [L, DI]  (SIMT, small K)
        launch_gemm_nt(xdbl, XDBLW, l_dtw, DTR, delta, DI, nullptr, l_dtb, L, DI, DTR, 1);
        // chunked selective scan -> y (fused +u*D and *silu(res))
        scan_phase1<<<dim3(DI / 128, NCHUNK), 128>>>(delta, xc, xdbl, l_alog, fin, prod);
        scan_combine<<<(DI * DS + 255) / 256, 256>>>(fin, prod, init);
        scan_phase2<<<dim3(DI / 128, NCHUNK), 128>>>(delta, xc, xdbl, l_alog, init, l_dp, xr, y);
        // h = h + y @ out_proj^T   (tensor core tf32, fused residual)
        launch_gemm_tf32(y, l_outw, h, h, L, NE, DI);
    }

    // final norm + tied lm head (tensor core tf32)
    rmsnorm_kernel<<<L, 256>>>(h, nfw, nfb, xn);
    launch_gemm_tf32(xn, E, logits, nullptr, L, 32000, NE);
}

// round 4
// speedup vs baseline: 3.0555x; 1.1952x over previous
#include <cuda_runtime.h>
#include <cuda_bf16.h>
#include <cstdint>
#include <cstddef>

#define L      2048
#define NE     768
#define DI     1536
#define DS     16
#define DTR    48
#define XPAD   128   // padded xdbl row stride
#define NCHUNK 64
#define CH     32    // NCHUNK*CH == L

// ---------------- scratch (static device globals; no allocation) ----------------
__device__ float g_h[L * NE];
__device__ float g_xn[L * NE];
__device__ float g_xr[L * 2 * DI];
__device__ float g_xc[L * DI];
__device__ float g_xdbl[L * XPAD];        // cols: 0..47 dt_lowrank, 48..63 B, 64..79 C, 80..127 zero-product
__device__ float g_delta[L * DI];
__device__ float g_y[L * DI];
__device__ float g_fin[NCHUNK * DI * DS];
__device__ float g_prod[NCHUNK * DI * DS];
__device__ float g_init[NCHUNK * DI * DS];
__device__ float g_xpw_pad[128 * DI];     // x_proj_w padded 80 -> 128 rows
__device__ float g_dtw_pad[DI * 64];      // dt_proj_w padded 48 -> 64 cols

// ---------------- helpers ----------------
__device__ __forceinline__ uint32_t smem_u32(const void* p) {
    uint32_t a;
    asm("{ .reg .u64 t; cvta.to.shared.u64 t, %1; cvt.u32.u64 %0, t; }" : "=r"(a) : "l"(p));
    return a;
}
__device__ __forceinline__ void cp16(uint32_t s, const void* g) {
    asm volatile("cp.async.cg.shared.global [%0], [%1], 16;" :: "r"(s), "l"(g));
}
__device__ __forceinline__ void cp_commit() {
    asm volatile("cp.async.commit_group;" ::: "memory");
}
__device__ __forceinline__ uint32_t f2tf(float x) {
    uint32_t r;
    asm("cvt.rna.tf32.f32 %0, %1;" : "=r"(r) : "f"(x));
    return r;
}
__device__ __forceinline__ float sigmoid_mul(float x) { return x / (1.f + __expf(-x)); }
__device__ __forceinline__ float softplus_f(float x) {
    return fmaxf(x, 0.f) + log1pf(__expf(-fabsf(x)));
}

// ---------------- embedding ----------------
__global__ void embed_kernel(const int* __restrict__ tok, const float* __restrict__ E,
                             float* __restrict__ h) {
    int i = blockIdx.x * 256 + threadIdx.x;
    if (i < L * NE) {
        int t = i / NE, e = i - t * NE;
        h[i] = E[(size_t)tok[t] * NE + e];
    }
}

// ---------------- rmsnorm ----------------
__global__ void rmsnorm_kernel(const float* __restrict__ in, const float* __restrict__ w,
                               const float* __restrict__ b, float* __restrict__ out) {
    int t = blockIdx.x;
    const float* row = in + (size_t)t * NE;
    float s = 0.f;
    for (int i = threadIdx.x; i < NE; i += 256) { float v = row[i]; s += v * v; }
    __shared__ float red[256];
    red[threadIdx.x] = s;
    __syncthreads();
    for (int st = 128; st > 0; st >>= 1) {
        if (threadIdx.x < st) red[threadIdx.x] += red[threadIdx.x + st];
        __syncthreads();
    }
    float inv = rsqrtf(red[0] / (float)NE + 1e-5f);
    for (int i = threadIdx.x; i < NE; i += 256)
        out[(size_t)t * NE + i] = row[i] * inv * w[i] + b[i];
}

// ---------------- weight padding kernels ----------------
__global__ void pad_xpw_kernel(const float* __restrict__ src, float* __restrict__ dst) {
    int i = blockIdx.x * 256 + threadIdx.x;      // over 128*DI
    if (i >= 128 * DI) return;
    int row = i / DI, col = i - row * DI;
    dst[i] = (row < 80) ? src[(size_t)row * DI + col] : 0.f;
}
__global__ void pad_dtw_kernel(const float* __restrict__ src, float* __restrict__ dst) {
    int i = blockIdx.x * 256 + threadIdx.x;      // over DI*64
    if (i >= DI * 64) return;
    int row = i >> 6, col = i & 63;
    dst[i] = (col < DTR) ? src[(size_t)row * DTR + col] : 0.f;
}

// ======================================================================================
// Tensor-core tf32 GEMM via mma.sync:
//   C[M,N] = A[M,K] @ B[N,K]^T  (+bias, +softplus, +Res)
// CTA tile 128 x NT (NT = 128 or 256), 8 warps (2x4) of 64 x NT/4, BK=32,
// double-buffered cp.async staging. Requires M%128==0, N%NT==0, K%32==0.
// smem rows padded to 36 floats -> conflict-free fragment LDS.
// ======================================================================================
template <int NT>
__global__ __launch_bounds__(256, 1) void gemm_mma(
    const float* __restrict__ A, const float* __restrict__ B,
    float* __restrict__ C, const float* __restrict__ Res, const float* __restrict__ bias,
    int M, int N, int K, int lda, int ldb, int ldc, int act) {
    constexpr int JT = NT / 32;          // j-tiles per warp (8-wide each)
    constexpr int SA = 128 * 36;
    constexpr int SB = NT * 36;
    extern __shared__ float smem[];
    float* As = smem;                    // [2][128][36]
    float* Bs = smem + 2 * SA;           // [2][NT][36]

    const int tid = threadIdx.x, wid = tid >> 5, lane = tid & 31;
    const int wm = wid >> 2, wn = wid & 3;
    const int bm = blockIdx.x * 128, bn = blockIdx.y * NT;
    const int NC = K >> 5;
    const int r = lane >> 2, cq = lane & 3;

    float acc[4][JT][4];
#pragma unroll
    for (int i = 0; i < 4; i++)
#pragma unroll
        for (int j = 0; j < JT; j++)
#pragma unroll
            for (int q = 0; q < 4; q++) acc[i][j][q] = 0.f;

    const int srow = tid >> 3, scol = (tid & 7) * 4;

    auto stage = [&](int c, int b) {
        int k0 = c * 32;
        float* sa = As + b * SA;
        float* sb = Bs + b * SB;
#pragma unroll
        for (int i = 0; i < 4; i++) {
            int rr = srow + i * 32;
            cp16(smem_u32(sa + rr * 36 + scol), A + (size_t)(bm + rr) * lda + k0 + scol);
        }
#pragma unroll
        for (int i = 0; i < NT / 32; i++) {
            int rr = srow + i * 32;
            cp16(smem_u32(sb + rr * 36 + scol), B + (size_t)(bn + rr) * ldb + k0 + scol);
        }
        cp_commit();
    };

    stage(0, 0);
    for (int c = 0; c < NC; c++) {
        int buf = c & 1;
        if (c + 1 < NC) {
            stage(c + 1, buf ^ 1);
            asm volatile("cp.async.wait_group 1;" ::: "memory");
        } else {
            asm volatile("cp.async.wait_group 0;" ::: "memory");
        }
        __syncthreads();

        const float* sa = As + buf * SA + (wm * 64 + r) * 36;
        const float* sb = Bs + buf * SB + (wn * (NT / 4) + r) * 36;
#pragma unroll
        for (int ks = 0; ks < 4; ks++) {
            int k = ks * 8 + cq;
            uint32_t af[4][4];
#pragma unroll
            for (int i = 0; i < 4; i++) {
                const float* p = sa + i * 16 * 36 + k;
                af[i][0] = f2tf(p[0]);
                af[i][1] = f2tf(p[8 * 36]);
                af[i][2] = f2tf(p[4]);
                af[i][3] = f2tf(p[8 * 36 + 4]);
            }
            uint32_t bf[JT][2];
#pragma unroll
            for (int j = 0; j < JT; j++) {
                const float* p = sb + j * 8 * 36 + k;
                bf[j][0] = f2tf(p[0]);
                bf[j][1] = f2tf(p[4]);
            }
#pragma unroll
            for (int i = 0; i < 4; i++)
#pragma unroll
                for (int j = 0; j < JT; j++)
                    asm volatile(
                        "mma.sync.aligned.m16n8k8.row.col.f32.tf32.tf32.f32 "
                        "{%0,%1,%2,%3}, {%4,%5,%6,%7}, {%8,%9}, {%0,%1,%2,%3};"
                        : "+f"(acc[i][j][0]), "+f"(acc[i][j][1]),
                          "+f"(acc[i][j][2]), "+f"(acc[i][j][3])
                        : "r"(af[i][0]), "r"(af[i][1]), "r"(af[i][2]), "r"(af[i][3]),
                          "r"(bf[j][0]), "r"(bf[j][1]));
        }
        __syncthreads();
    }

    // epilogue
#pragma unroll
    for (int i = 0; i < 4; i++) {
        int r0 = bm + wm * 64 + i * 16 + r;
#pragma unroll
        for (int j = 0; j < JT; j++) {
            int c0 = bn + wn * (NT / 4) + j * 8 + cq * 2;
            float v00 = acc[i][j][0], v01 = acc[i][j][1];
            float v10 = acc[i][j][2], v11 = acc[i][j][3];
            if (bias) {
                float b0 = bias[c0], b1 = bias[c0 + 1];
                v00 += b0; v01 += b1; v10 += b0; v11 += b1;
            }
            if (act) {
                v00 = softplus_f(v00); v01 = softplus_f(v01);
                v10 = softplus_f(v10); v11 = softplus_f(v11);
            }
            if (Res) {
                float2 p0 = *(const float2*)&Res[(size_t)r0 * ldc + c0];
                float2 p1 = *(const float2*)&Res[(size_t)(r0 + 8) * ldc + c0];
                v00 += p0.x; v01 += p0.y;
                v10 += p1.x; v11 += p1.y;
            }
            *(float2*)&C[(size_t)r0 * ldc + c0] = make_float2(v00, v01);
            *(float2*)&C[(size_t)(r0 + 8) * ldc + c0] = make_float2(v10, v11);
        }
    }
}

#define SMEM_NT(NT) ((2 * 128 * 36 + 2 * (NT) * 36) * 4)

// ---------------- depthwise causal conv (d_conv=4) + bias + silu ----------------
__global__ void conv_silu_kernel(const float* __restrict__ xr, const float* __restrict__ cw,
                                 const float* __restrict__ cb, float* __restrict__ xc) {
    int i = blockIdx.x * 256 + threadIdx.x;
    if (i >= L * DI) return;
    int t = i / DI, d = i - t * DI;
    float acc = cb[d];
#pragma unroll
    for (int j = 0; j < 4; j++) {
        int ts = t - 3 + j;
        if (ts >= 0) acc = fmaf(cw[d * 4 + j], xr[(size_t)ts * (2 * DI) + d], acc);
    }
    xc[i] = sigmoid_mul(acc);
}

// ---------------- chunked selective scan ----------------
__global__ __launch_bounds__(128) void scan_phase1(
    const float* __restrict__ delta, const float* __restrict__ u,
    const float* __restrict__ xdbl, const float* __restrict__ A_log,
    float* __restrict__ fin, float* __restrict__ prod) {
    int p = blockIdx.y;
    int d = blockIdx.x * 128 + threadIdx.x;
    __shared__ float Bs[CH][DS];
    for (int i = threadIdx.x; i < CH * DS; i += 128) {
        int tt = i >> 4, n = i & 15;
        Bs[tt][n] = xdbl[(size_t)(p * CH + tt) * XPAD + 48 + n];
    }
    __syncthreads();
    float Aa[DS], x[DS], pa[DS];
#pragma unroll
    for (int n = 0; n < DS; n++) {
        Aa[n] = -__expf(A_log[(size_t)d * DS + n]);
        x[n] = 0.f;
        pa[n] = 1.f;
    }
    for (int tt = 0; tt < CH; tt++) {
        int t = p * CH + tt;
        float dl = delta[(size_t)t * DI + d];
        float uu = u[(size_t)t * DI + d];
        float du = dl * uu;
#pragma unroll
        for (int n = 0; n < DS; n++) {
            float e = __expf(dl * Aa[n]);
            x[n] = fmaf(e, x[n], du * Bs[tt][n]);
            pa[n] *= e;
        }
    }
    size_t base = (size_t)p * DI * DS + (size_t)d * DS;
#pragma unroll
    for (int n = 0; n < DS; n++) { fin[base + n] = x[n]; prod[base + n] = pa[n]; }
}

__global__ void scan_combine(const float* __restrict__ fin, const float* __restrict__ prod,
                             float* __restrict__ init) {
    int i = blockIdx.x * 256 + threadIdx.x;
    if (i >= DI * DS) return;
    float s = 0.f;
#pragma unroll 4
    for (int p = 0; p < NCHUNK; p++) {
        size_t idx = (size_t)p * DI * DS + i;
        init[idx] = s;
        s = fmaf(prod[idx], s, fin[idx]);
    }
}

__global__ __launch_bounds__(128) void scan_phase2(
    const float* __restrict__ delta, const float* __restrict__ u,
    const float* __restrict__ xdbl, const float* __restrict__ A_log,
    const float* __restrict__ init, const float* __restrict__ Dp,
    const float* __restrict__ xr, float* __restrict__ yout) {
    int p = blockIdx.y;
    int d = blockIdx.x * 128 + threadIdx.x;
    __shared__ float Bs[CH][DS];
    __shared__ float Cs[CH][DS];
    for (int i = threadIdx.x; i < CH * DS; i += 128) {
        int tt = i >> 4, n = i & 15;
        size_t row = (size_t)(p * CH + tt) * XPAD;
        Bs[tt][n] = xdbl[row + 48 + n];
        Cs[tt][n] = xdbl[row + 64 + n];
    }
    __syncthreads();
    float Aa[DS], x[DS];
    size_t base = (size_t)p * DI * DS + (size_t)d * DS;
#pragma unroll
    for (int n = 0; n < DS; n++) {
        Aa[n] = -__expf(A_log[(size_t)d * DS + n]);
        x[n] = init[base + n];
    }
    float Dd = Dp[d];
    for (int tt = 0; tt < CH; tt++) {
        int t = p * CH + tt;
        float dl = delta[(size_t)t * DI + d];
        float uu = u[(size_t)t * DI + d];
        float du = dl * uu;
        float y0 = 0.f, y1 = 0.f, y2 = 0.f, y3 = 0.f;
#pragma unroll
        for (int n = 0; n < DS; n++) {
            float e = __expf(dl * Aa[n]);
            x[n] = fmaf(e, x[n], du * Bs[tt][n]);
            float pr = x[n] * Cs[tt][n];
            if ((n & 3) == 0) y0 += pr;
            else if ((n & 3) == 1) y1 += pr;
            else if ((n & 3) == 2) y2 += pr;
            else y3 += pr;
        }
        float y = (y0 + y1) + (y2 + y3) + uu * Dd;
        float r = xr[(size_t)t * (2 * DI) + DI + d];
        yout[(size_t)t * DI + d] = y * sigmoid_mul(r);
    }
}

// ---------------- host orchestration ----------------
template <int NT>
static void launch_mma(const float* A, const float* B, float* C,
                       const float* Res, const float* bias,
                       int M, int N, int K, int lda, int ldb, int ldc, int act) {
    dim3 grid(M / 128, N / NT);   // M fast -> CTA waves share one B column-panel
    gemm_mma<NT><<<grid, 256, SMEM_NT(NT)>>>(A, B, C, Res, bias, M, N, K, lda, ldb, ldc, act);
}

extern "C" void kernel_launch(void* const* d_in, const int* in_sizes, int n_in,
                              void* d_out, int out_size) {
    const int*   tokens = (const int*)d_in[0];
    const float* E      = (const float*)d_in[1];
    const float* in_w   = (const float*)d_in[2];
    const float* conv_w = (const float*)d_in[3];
    const float* conv_b = (const float*)d_in[4];
    const float* xp_w   = (const float*)d_in[5];
    const float* dt_w   = (const float*)d_in[6];
    const float* dt_b   = (const float*)d_in[7];
    const float* A_log  = (const float*)d_in[8];
    const float* Dp     = (const float*)d_in[9];
    const float* out_w  = (const float*)d_in[10];
    const float* nw     = (const float*)d_in[11];
    const float* nb     = (const float*)d_in[12];
    const float* nfw    = (const float*)d_in[13];
    const float* nfb    = (const float*)d_in[14];
    float* logits = (float*)d_out;

    float *h, *xn, *xr, *xc, *xdbl, *delta, *y, *fin, *prod, *init, *xpwp, *dtwp;
    cudaGetSymbolAddress((void**)&h, g_h);
    cudaGetSymbolAddress((void**)&xn, g_xn);
    cudaGetSymbolAddress((void**)&xr, g_xr);
    cudaGetSymbolAddress((void**)&xc, g_xc);
    cudaGetSymbolAddress((void**)&xdbl, g_xdbl);
    cudaGetSymbolAddress((void**)&delta, g_delta);
    cudaGetSymbolAddress((void**)&y, g_y);
    cudaGetSymbolAddress((void**)&fin, g_fin);
    cudaGetSymbolAddress((void**)&prod, g_prod);
    cudaGetSymbolAddress((void**)&init, g_init);
    cudaGetSymbolAddress((void**)&xpwp, g_xpw_pad);
    cudaGetSymbolAddress((void**)&dtwp, g_dtw_pad);

    cudaFuncSetAttribute(gemm_mma<256>, cudaFuncAttributeMaxDynamicSharedMemorySize, SMEM_NT(256));
    cudaFuncSetAttribute(gemm_mma<128>, cudaFuncAttributeMaxDynamicSharedMemorySize, SMEM_NT(128));

    embed_kernel<<<(L * NE + 255) / 256, 256>>>(tokens, E, h);

    for (int l = 0; l < 2; l++) {
        const float* l_inw  = in_w  + (size_t)l * (2 * DI) * NE;
        const float* l_cw   = conv_w + (size_t)l * DI * 4;
        const float* l_cb   = conv_b + (size_t)l * DI;
        const float* l_xpw  = xp_w  + (size_t)l * 80 * DI;
        const float* l_dtw  = dt_w  + (size_t)l * DI * DTR;
        const float* l_dtb  = dt_b  + (size_t)l * DI;
        const float* l_alog = A_log + (size_t)l * DI * DS;
        const float* l_dp   = Dp    + (size_t)l * DI;
        const float* l_outw = out_w + (size_t)l * NE * DI;

        // pad per-layer weights for MMA-friendly shapes
        pad_xpw_kernel<<<(128 * DI + 255) / 256, 256>>>(l_xpw, xpwp);
        pad_dtw_kernel<<<(DI * 64 + 255) / 256, 256>>>(l_dtw, dtwp);

        // xn = rmsnorm(h)
        rmsnorm_kernel<<<L, 256>>>(h, nw + l * NE, nb + l * NE, xn);
        // xr = xn @ in_proj^T  [L, 3072]
        launch_mma<256>(xn, l_inw, xr, nullptr, nullptr, L, 2 * DI, NE, NE, NE, 2 * DI, 0);
        // xc = silu(depthwise causal conv(x) + b)
        conv_silu_kernel<<<(L * DI + 255) / 256, 256>>>(xr, l_cw, l_cb, xc);
        // xdbl = xc @ xpw_pad^T  [L, 128]  (cols 80..127 are zero-weight products)
        launch_mma<128>(xc, xpwp, xdbl, nullptr, nullptr, L, XPAD, DI, DI, DI, XPAD, 0);
        // delta = softplus(xdbl[:, :64] @ dtw_pad^T + dt_b)  [L, 1536]
        //         (xdbl cols 48..63 hit zero columns of dtw_pad -> no contribution)
        launch_mma<256>(xdbl, dtwp, delta, nullptr, l_dtb, L, DI, 64, XPAD, 64, DI, 1);
        // chunked selective scan -> y (fused +u*D and *silu(res))
        scan_phase1<<<dim3(DI / 128, NCHUNK), 128>>>(delta, xc, xdbl, l_alog, fin, prod);
        scan_combine<<<(DI * DS + 255) / 256, 256>>>(fin, prod, init);
        scan_phase2<<<dim3(DI / 128, NCHUNK), 128>>>(delta, xc, xdbl, l_alog, init, l_dp, xr, y);
        // h = h + y @ out_proj^T
        launch_mma<256>(y, l_outw, h, h, nullptr, L, NE, DI, DI, DI, NE, 0);
    }

    // final norm + tied lm head
    rmsnorm_kernel<<<L, 256>>>(h, nfw, nfb, xn);
    launch_mma<256>(xn, E, logits, nullptr, nullptr, L, 32000, NE, NE, NE, 32000, 0);
}

// round 5
// speedup vs baseline: 3.2687x; 1.0698x over previous
#include <cuda_runtime.h>
#include <cuda_bf16.h>
#include <cstdint>
#include <cstddef>

#define L      2048
#define NE     768
#define DI     1536
#define DS     16
#define DTR    48
#define XPAD   128   // padded xdbl row stride
#define NCHUNK 64
#define CH     32    // NCHUNK*CH == L

// ---------------- scratch (static device globals; no allocation) ----------------
__device__ float g_h[L * NE];
__device__ float g_xn[L * NE];
__device__ float g_xr[L * 2 * DI];
__device__ float g_xc[L * DI];
__device__ float g_xdbl[L * XPAD];        // cols: 0..47 dt_lowrank, 48..63 B, 64..79 C, 80..127 pad
__device__ float g_delta[L * DI];
__device__ float g_y[L * DI];
__device__ float g_fin[NCHUNK * DI * DS];
__device__ float g_prod[NCHUNK * DI * DS];
__device__ float g_init[NCHUNK * DI * DS];
__device__ float g_xpw_pad[128 * DI];     // x_proj_w padded 80 -> 128 rows
__device__ float g_dtw_pad[DI * 64];      // dt_proj_w padded 48 -> 64 cols

// ---------------- helpers ----------------
__device__ __forceinline__ uint32_t smem_u32(const void* p) {
    uint32_t a;
    asm("{ .reg .u64 t; cvta.to.shared.u64 t, %1; cvt.u32.u64 %0, t; }" : "=r"(a) : "l"(p));
    return a;
}
__device__ __forceinline__ void cp16(uint32_t s, const void* g) {
    asm volatile("cp.async.cg.shared.global [%0], [%1], 16;" :: "r"(s), "l"(g));
}
__device__ __forceinline__ void cp_commit() {
    asm volatile("cp.async.commit_group;" ::: "memory");
}
__device__ __forceinline__ uint32_t f2tf(uint32_t bits) {
    uint32_t r;
    asm("cvt.rna.tf32.f32 %0, %1;" : "=r"(r) : "f"(__uint_as_float(bits)));
    return r;
}
#define LDSM4(r0, r1, r2, r3, addr) \
    asm volatile("ldmatrix.sync.aligned.m8n8.x4.shared.b16 {%0,%1,%2,%3}, [%4];" \
                 : "=r"(r0), "=r"(r1), "=r"(r2), "=r"(r3) : "r"(addr))

__device__ __forceinline__ float sigmoid_mul(float x) { return x / (1.f + __expf(-x)); }
__device__ __forceinline__ float softplus_f(float x) {
    return fmaxf(x, 0.f) + log1pf(__expf(-fabsf(x)));
}

// ---------------- embedding ----------------
__global__ void embed_kernel(const int* __restrict__ tok, const float* __restrict__ E,
                             float* __restrict__ h) {
    int i = blockIdx.x * 256 + threadIdx.x;
    if (i < L * NE) {
        int t = i / NE, e = i - t * NE;
        h[i] = E[(size_t)tok[t] * NE + e];
    }
}

// ---------------- rmsnorm ----------------
__global__ void rmsnorm_kernel(const float* __restrict__ in, const float* __restrict__ w,
                               const float* __restrict__ b, float* __restrict__ out) {
    int t = blockIdx.x;
    const float* row = in + (size_t)t * NE;
    float s = 0.f;
    for (int i = threadIdx.x; i < NE; i += 256) { float v = row[i]; s += v * v; }
    __shared__ float red[256];
    red[threadIdx.x] = s;
    __syncthreads();
    for (int st = 128; st > 0; st >>= 1) {
        if (threadIdx.x < st) red[threadIdx.x] += red[threadIdx.x + st];
        __syncthreads();
    }
    float inv = rsqrtf(red[0] / (float)NE + 1e-5f);
    for (int i = threadIdx.x; i < NE; i += 256)
        out[(size_t)t * NE + i] = row[i] * inv * w[i] + b[i];
}

// ---------------- weight padding kernels ----------------
__global__ void pad_xpw_kernel(const float* __restrict__ src, float* __restrict__ dst) {
    int i = blockIdx.x * 256 + threadIdx.x;      // over 128*DI
    if (i >= 128 * DI) return;
    int row = i / DI, col = i - row * DI;
    dst[i] = (row < 80) ? src[(size_t)row * DI + col] : 0.f;
}
__global__ void pad_dtw_kernel(const float* __restrict__ src, float* __restrict__ dst) {
    int i = blockIdx.x * 256 + threadIdx.x;      // over DI*64
    if (i >= DI * 64) return;
    int row = i >> 6, col = i & 63;
    dst[i] = (col < DTR) ? src[(size_t)row * DTR + col] : 0.f;
}

// ======================================================================================
// Tensor-core tf32 GEMM via mma.sync + ldmatrix:
//   C[M,N] = A[M,K] @ B[N,K]^T  (+bias, +softplus, +Res)
// CTA tile 128 x NT (128 or 256), 8 warps (2x4) of 64 x NT/4, BK=32,
// double-buffered cp.async staging, LDSM.x4 fragment loads.
// Requires M%128==0, N%NT==0, K%32==0. smem rows padded to 36 floats -> LDSM conflict-free.
// ======================================================================================
template <int NT>
__global__ __launch_bounds__(256, 1) void gemm_mma(
    const float* __restrict__ A, const float* __restrict__ B,
    float* __restrict__ C, const float* __restrict__ Res, const float* __restrict__ bias,
    int M, int N, int K, int lda, int ldb, int ldc, int act) {
    constexpr int JT = NT / 32;          // j-tiles per warp (8-wide each)
    constexpr int SA = 128 * 36;
    constexpr int SB = NT * 36;
    extern __shared__ float smem[];
    float* As = smem;                    // [2][128][36]
    float* Bs = smem + 2 * SA;           // [2][NT][36]

    const int tid = threadIdx.x, wid = tid >> 5, lane = tid & 31;
    const int wm = wid >> 2, wn = wid & 3;
    const int bm = blockIdx.x * 128, bn = blockIdx.y * NT;
    const int NC = K >> 5;
    const int r = lane >> 2, cq = lane & 3;
    const int rowin = lane & 7, tsel = lane >> 3;

    float acc[4][JT][4];
#pragma unroll
    for (int i = 0; i < 4; i++)
#pragma unroll
        for (int j = 0; j < JT; j++)
#pragma unroll
            for (int q = 0; q < 4; q++) acc[i][j][q] = 0.f;

    const int srow = tid >> 3, scol = (tid & 7) * 4;

    auto stage = [&](int c, int b) {
        int k0 = c * 32;
        float* sa = As + b * SA;
        float* sb = Bs + b * SB;
#pragma unroll
        for (int i = 0; i < 4; i++) {
            int rr = srow + i * 32;
            cp16(smem_u32(sa + rr * 36 + scol), A + (size_t)(bm + rr) * lda + k0 + scol);
        }
#pragma unroll
        for (int i = 0; i < NT / 32; i++) {
            int rr = srow + i * 32;
            cp16(smem_u32(sb + rr * 36 + scol), B + (size_t)(bn + rr) * ldb + k0 + scol);
        }
        cp_commit();
    };

    // per-thread LDSM base offsets (floats) within a buffer
    // A tiles: t0=(rows+0,klo) t1=(rows+8,klo) t2=(rows+0,khi) t3=(rows+8,khi)
    const int a_off = (wm * 64 + rowin + (tsel & 1) * 8) * 36 + (tsel >> 1) * 4;
    // B tiles: t0=(j0,klo) t1=(j0,khi) t2=(j1,klo) t3=(j1,khi)
    const int b_off = (wn * (NT / 4) + rowin + (tsel >> 1) * 8) * 36 + (tsel & 1) * 4;

    stage(0, 0);
    for (int c = 0; c < NC; c++) {
        int buf = c & 1;
        if (c + 1 < NC) {
            stage(c + 1, buf ^ 1);
            asm volatile("cp.async.wait_group 1;" ::: "memory");
        } else {
            asm volatile("cp.async.wait_group 0;" ::: "memory");
        }
        __syncthreads();

        const uint32_t abase = smem_u32(As + buf * SA + a_off);
        const uint32_t bbase = smem_u32(Bs + buf * SB + b_off);
#pragma unroll
        for (int ks = 0; ks < 4; ks++) {
            uint32_t af[4][4];
#pragma unroll
            for (int i = 0; i < 4; i++) {
                LDSM4(af[i][0], af[i][1], af[i][2], af[i][3],
                      abase + (uint32_t)(i * 16 * 36 + ks * 8) * 4u);
                af[i][0] = f2tf(af[i][0]); af[i][1] = f2tf(af[i][1]);
                af[i][2] = f2tf(af[i][2]); af[i][3] = f2tf(af[i][3]);
            }
            uint32_t bf[JT][2];
#pragma unroll
            for (int jp = 0; jp < JT / 2; jp++) {
                LDSM4(bf[2 * jp][0], bf[2 * jp][1], bf[2 * jp + 1][0], bf[2 * jp + 1][1],
                      bbase + (uint32_t)(jp * 16 * 36 + ks * 8) * 4u);
                bf[2 * jp][0] = f2tf(bf[2 * jp][0]);
                bf[2 * jp][1] = f2tf(bf[2 * jp][1]);
                bf[2 * jp + 1][0] = f2tf(bf[2 * jp + 1][0]);
                bf[2 * jp + 1][1] = f2tf(bf[2 * jp + 1][1]);
            }
#pragma unroll
            for (int i = 0; i < 4; i++)
#pragma unroll
                for (int j = 0; j < JT; j++)
                    asm volatile(
                        "mma.sync.aligned.m16n8k8.row.col.f32.tf32.tf32.f32 "
                        "{%0,%1,%2,%3}, {%4,%5,%6,%7}, {%8,%9}, {%0,%1,%2,%3};"
                        : "+f"(acc[i][j][0]), "+f"(acc[i][j][1]),
                          "+f"(acc[i][j][2]), "+f"(acc[i][j][3])
                        : "r"(af[i][0]), "r"(af[i][1]), "r"(af[i][2]), "r"(af[i][3]),
                          "r"(bf[j][0]), "r"(bf[j][1]));
        }
        __syncthreads();
    }

    // epilogue
#pragma unroll
    for (int i = 0; i < 4; i++) {
        int r0 = bm + wm * 64 + i * 16 + r;
#pragma unroll
        for (int j = 0; j < JT; j++) {
            int c0 = bn + wn * (NT / 4) + j * 8 + cq * 2;
            float v00 = acc[i][j][0], v01 = acc[i][j][1];
            float v10 = acc[i][j][2], v11 = acc[i][j][3];
            if (bias) {
                float b0 = bias[c0], b1 = bias[c0 + 1];
                v00 += b0; v01 += b1; v10 += b0; v11 += b1;
            }
            if (act) {
                v00 = softplus_f(v00); v01 = softplus_f(v01);
                v10 = softplus_f(v10); v11 = softplus_f(v11);
            }
            if (Res) {
                float2 p0 = *(const float2*)&Res[(size_t)r0 * ldc + c0];
                float2 p1 = *(const float2*)&Res[(size_t)(r0 + 8) * ldc + c0];
                v00 += p0.x; v01 += p0.y;
                v10 += p1.x; v11 += p1.y;
            }
            *(float2*)&C[(size_t)r0 * ldc + c0] = make_float2(v00, v01);
            *(float2*)&C[(size_t)(r0 + 8) * ldc + c0] = make_float2(v10, v11);
        }
    }
}

#define SMEM_NT(NT) ((2 * 128 * 36 + 2 * (NT) * 36) * 4)

// ---------------- depthwise causal conv (d_conv=4) + bias + silu ----------------
__global__ void conv_silu_kernel(const float* __restrict__ xr, const float* __restrict__ cw,
                                 const float* __restrict__ cb, float* __restrict__ xc) {
    int i = blockIdx.x * 256 + threadIdx.x;
    if (i >= L * DI) return;
    int t = i / DI, d = i - t * DI;
    float acc = cb[d];
#pragma unroll
    for (int j = 0; j < 4; j++) {
        int ts = t - 3 + j;
        if (ts >= 0) acc = fmaf(cw[d * 4 + j], xr[(size_t)ts * (2 * DI) + d], acc);
    }
    xc[i] = sigmoid_mul(acc);
}

// ---------------- chunked selective scan ----------------
__global__ __launch_bounds__(128) void scan_phase1(
    const float* __restrict__ delta, const float* __restrict__ u,
    const float* __restrict__ xdbl, const float* __restrict__ A_log,
    float* __restrict__ fin, float* __restrict__ prod) {
    int p = blockIdx.y;
    int d = blockIdx.x * 128 + threadIdx.x;
    __shared__ float Bs[CH][DS];
    for (int i = threadIdx.x; i < CH * DS; i += 128) {
        int tt = i >> 4, n = i & 15;
        Bs[tt][n] = xdbl[(size_t)(p * CH + tt) * XPAD + 48 + n];
    }
    __syncthreads();
    float Aa[DS], x[DS], pa[DS];
#pragma unroll
    for (int n = 0; n < DS; n++) {
        Aa[n] = -__expf(A_log[(size_t)d * DS + n]);
        x[n] = 0.f;
        pa[n] = 1.f;
    }
    for (int tt = 0; tt < CH; tt++) {
        int t = p * CH + tt;
        float dl = delta[(size_t)t * DI + d];
        float uu = u[(size_t)t * DI + d];
        float du = dl * uu;
#pragma unroll
        for (int n = 0; n < DS; n++) {
            float e = __expf(dl * Aa[n]);
            x[n] = fmaf(e, x[n], du * Bs[tt][n]);
            pa[n] *= e;
        }
    }
    size_t base = (size_t)p * DI * DS + (size_t)d * DS;
#pragma unroll
    for (int n = 0; n < DS; n++) { fin[base + n] = x[n]; prod[base + n] = pa[n]; }
}

__global__ void scan_combine(const float* __restrict__ fin, const float* __restrict__ prod,
                             float* __restrict__ init) {
    int i = blockIdx.x * 256 + threadIdx.x;
    if (i >= DI * DS) return;
    float s = 0.f;
#pragma unroll 4
    for (int p = 0; p < NCHUNK; p++) {
        size_t idx = (size_t)p * DI * DS + i;
        init[idx] = s;
        s = fmaf(prod[idx], s, fin[idx]);
    }
}

__global__ __launch_bounds__(128) void scan_phase2(
    const float* __restrict__ delta, const float* __restrict__ u,
    const float* __restrict__ xdbl, const float* __restrict__ A_log,
    const float* __restrict__ init, const float* __restrict__ Dp,
    const float* __restrict__ xr, float* __restrict__ yout) {
    int p = blockIdx.y;
    int d = blockIdx.x * 128 + threadIdx.x;
    __shared__ float Bs[CH][DS];
    __shared__ float Cs[CH][DS];
    for (int i = threadIdx.x; i < CH * DS; i += 128) {
        int tt = i >> 4, n = i & 15;
        size_t row = (size_t)(p * CH + tt) * XPAD;
        Bs[tt][n] = xdbl[row + 48 + n];
        Cs[tt][n] = xdbl[row + 64 + n];
    }
    __syncthreads();
    float Aa[DS], x[DS];
    size_t base = (size_t)p * DI * DS + (size_t)d * DS;
#pragma unroll
    for (int n = 0; n < DS; n++) {
        Aa[n] = -__expf(A_log[(size_t)d * DS + n]);
        x[n] = init[base + n];
    }
    float Dd = Dp[d];
    for (int tt = 0; tt < CH; tt++) {
        int t = p * CH + tt;
        float dl = delta[(size_t)t * DI + d];
        float uu = u[(size_t)t * DI + d];
        float du = dl * uu;
        float y0 = 0.f, y1 = 0.f, y2 = 0.f, y3 = 0.f;
#pragma unroll
        for (int n = 0; n < DS; n++) {
            float e = __expf(dl * Aa[n]);
            x[n] = fmaf(e, x[n], du * Bs[tt][n]);
            float pr = x[n] * Cs[tt][n];
            if ((n & 3) == 0) y0 += pr;
            else if ((n & 3) == 1) y1 += pr;
            else if ((n & 3) == 2) y2 += pr;
            else y3 += pr;
        }
        float y = (y0 + y1) + (y2 + y3) + uu * Dd;
        float r = xr[(size_t)t * (2 * DI) + DI + d];
        yout[(size_t)t * DI + d] = y * sigmoid_mul(r);
    }
}

// ---------------- host orchestration ----------------
template <int NT>
static void launch_mma(const float* A, const float* B, float* C,
                       const float* Res, const float* bias,
                       int M, int N, int K, int lda, int ldb, int ldc, int act) {
    dim3 grid(M / 128, N / NT);   // M fast -> CTA waves share one B column-panel
    gemm_mma<NT><<<grid, 256, SMEM_NT(NT)>>>(A, B, C, Res, bias, M, N, K, lda, ldb, ldc, act);
}

extern "C" void kernel_launch(void* const* d_in, const int* in_sizes, int n_in,
                              void* d_out, int out_size) {
    const int*   tokens = (const int*)d_in[0];
    const float* E      = (const float*)d_in[1];
    const float* in_w   = (const float*)d_in[2];
    const float* conv_w = (const float*)d_in[3];
    const float* conv_b = (const float*)d_in[4];
    const float* xp_w   = (const float*)d_in[5];
    const float* dt_w   = (const float*)d_in[6];
    const float* dt_b   = (const float*)d_in[7];
    const float* A_log  = (const float*)d_in[8];
    const float* Dp     = (const float*)d_in[9];
    const float* out_w  = (const float*)d_in[10];
    const float* nw     = (const float*)d_in[11];
    const float* nb     = (const float*)d_in[12];
    const float* nfw    = (const float*)d_in[13];
    const float* nfb    = (const float*)d_in[14];
    float* logits = (float*)d_out;

    float *h, *xn, *xr, *xc, *xdbl, *delta, *y, *fin, *prod, *init, *xpwp, *dtwp;
    cudaGetSymbolAddress((void**)&h, g_h);
    cudaGetSymbolAddress((void**)&xn, g_xn);
    cudaGetSymbolAddress((void**)&xr, g_xr);
    cudaGetSymbolAddress((void**)&xc, g_xc);
    cudaGetSymbolAddress((void**)&xdbl, g_xdbl);
    cudaGetSymbolAddress((void**)&delta, g_delta);
    cudaGetSymbolAddress((void**)&y, g_y);
    cudaGetSymbolAddress((void**)&fin, g_fin);
    cudaGetSymbolAddress((void**)&prod, g_prod);
    cudaGetSymbolAddress((void**)&init, g_init);
    cudaGetSymbolAddress((void**)&xpwp, g_xpw_pad);
    cudaGetSymbolAddress((void**)&dtwp, g_dtw_pad);

    cudaFuncSetAttribute(gemm_mma<256>, cudaFuncAttributeMaxDynamicSharedMemorySize, SMEM_NT(256));
    cudaFuncSetAttribute(gemm_mma<128>, cudaFuncAttributeMaxDynamicSharedMemorySize, SMEM_NT(128));

    embed_kernel<<<(L * NE + 255) / 256, 256>>>(tokens, E, h);

    for (int l = 0; l < 2; l++) {
        const float* l_inw  = in_w  + (size_t)l * (2 * DI) * NE;
        const float* l_cw   = conv_w + (size_t)l * DI * 4;
        const float* l_cb   = conv_b + (size_t)l * DI;
        const float* l_xpw  = xp_w  + (size_t)l * 80 * DI;
        const float* l_dtw  = dt_w  + (size_t)l * DI * DTR;
        const float* l_dtb  = dt_b  + (size_t)l * DI;
        const float* l_alog = A_log + (size_t)l * DI * DS;
        const float* l_dp   = Dp    + (size_t)l * DI;
        const float* l_outw = out_w + (size_t)l * NE * DI;

        // pad per-layer weights for MMA-friendly shapes
        pad_xpw_kernel<<<(128 * DI + 255) / 256, 256>>>(l_xpw, xpwp);
        pad_dtw_kernel<<<(DI * 64 + 255) / 256, 256>>>(l_dtw, dtwp);

        // xn = rmsnorm(h)
        rmsnorm_kernel<<<L, 256>>>(h, nw + l * NE, nb + l * NE, xn);
        // xr = xn @ in_proj^T  [L, 3072]
        launch_mma<256>(xn, l_inw, xr, nullptr, nullptr, L, 2 * DI, NE, NE, NE, 2 * DI, 0);
        // xc = silu(depthwise causal conv(x) + b)
        conv_silu_kernel<<<(L * DI + 255) / 256, 256>>>(xr, l_cw, l_cb, xc);
        // xdbl = xc @ xpw_pad^T  [L, 128]
        launch_mma<128>(xc, xpwp, xdbl, nullptr, nullptr, L, XPAD, DI, DI, DI, XPAD, 0);
        // delta = softplus(xdbl[:, :64] @ dtw_pad^T + dt_b)  [L, 1536]
        launch_mma<256>(xdbl, dtwp, delta, nullptr, l_dtb, L, DI, 64, XPAD, 64, DI, 1);
        // chunked selective scan -> y (fused +u*D and *silu(res))
        scan_phase1<<<dim3(DI / 128, NCHUNK), 128>>>(delta, xc, xdbl, l_alog, fin, prod);
        scan_combine<<<(DI * DS + 255) / 256, 256>>>(fin, prod, init);
        scan_phase2<<<dim3(DI / 128, NCHUNK), 128>>>(delta, xc, xdbl, l_alog, init, l_dp, xr, y);
        // h = h + y @ out_proj^T
        launch_mma<256>(y, l_outw, h, h, nullptr, L, NE, DI, DI, DI, NE, 0);
    }

    // final norm + tied lm head
    rmsnorm_kernel<<<L, 256>>>(h, nfw, nfb, xn);
    launch_mma<256>(xn, E, logits, nullptr, nullptr, L, 32000, NE, NE, NE, 32000, 0);
}

// round 6
// speedup vs baseline: 4.2857x; 1.3112x over previous
#include <cuda_runtime.h>
#include <cuda_fp16.h>
#include <cstdint>
#include <cstddef>

#define L      2048
#define NE     768
#define DI     1536
#define DS     16
#define DTR    48
#define XPAD   128   // padded xdbl row stride
#define NCHUNK 64
#define CH     32    // NCHUNK*CH == L

// ---------------- scratch (static device globals; no allocation) ----------------
__device__ float g_h[L * NE];
__device__ float g_xn[L * NE];
__device__ float g_xr[L * 2 * DI];
__device__ float g_xc[L * DI];
__device__ float g_xdbl[L * XPAD];
__device__ float g_delta[L * DI];
__device__ float g_y[L * DI];
__device__ float g_fin[NCHUNK * DI * DS];
__device__ float g_prod[NCHUNK * DI * DS];
__device__ float g_init[NCHUNK * DI * DS];
__device__ float g_xpw_pad[128 * DI];     // x_proj_w padded 80 -> 128 rows
__device__ float g_dtw_pad[DI * 64];      // dt_proj_w padded 48 -> 64 cols
__device__ __half g_ah[L * DI];           // fp16 activations (max L*DI)
__device__ __half g_wh[32000 * NE];       // fp16 weights (max vocab*NE)

// ---------------- helpers ----------------
__device__ __forceinline__ uint32_t smem_u32(const void* p) {
    uint32_t a;
    asm("{ .reg .u64 t; cvta.to.shared.u64 t, %1; cvt.u32.u64 %0, t; }" : "=r"(a) : "l"(p));
    return a;
}
__device__ __forceinline__ void cp16(uint32_t s, const void* g) {
    asm volatile("cp.async.cg.shared.global [%0], [%1], 16;" :: "r"(s), "l"(g));
}
__device__ __forceinline__ void cp_commit() {
    asm volatile("cp.async.commit_group;" ::: "memory");
}
__device__ __forceinline__ uint32_t f2tf(uint32_t bits) {
    uint32_t r;
    asm("cvt.rna.tf32.f32 %0, %1;" : "=r"(r) : "f"(__uint_as_float(bits)));
    return r;
}
#define LDSM4(r0, r1, r2, r3, addr) \
    asm volatile("ldmatrix.sync.aligned.m8n8.x4.shared.b16 {%0,%1,%2,%3}, [%4];" \
                 : "=r"(r0), "=r"(r1), "=r"(r2), "=r"(r3) : "r"(addr))

__device__ __forceinline__ float sigmoid_mul(float x) { return x / (1.f + __expf(-x)); }
__device__ __forceinline__ float softplus_f(float x) {
    return fmaxf(x, 0.f) + log1pf(__expf(-fabsf(x)));
}

// ---------------- embedding ----------------
__global__ void embed_kernel(const int* __restrict__ tok, const float* __restrict__ E,
                             float* __restrict__ h) {
    int i = blockIdx.x * 256 + threadIdx.x;
    if (i < L * NE) {
        int t = i / NE, e = i - t * NE;
        h[i] = E[(size_t)tok[t] * NE + e];
    }
}

// ---------------- rmsnorm ----------------
__global__ void rmsnorm_kernel(const float* __restrict__ in, const float* __restrict__ w,
                               const float* __restrict__ b, float* __restrict__ out) {
    int t = blockIdx.x;
    const float* row = in + (size_t)t * NE;
    float s = 0.f;
    for (int i = threadIdx.x; i < NE; i += 256) { float v = row[i]; s += v * v; }
    __shared__ float red[256];
    red[threadIdx.x] = s;
    __syncthreads();
    for (int st = 128; st > 0; st >>= 1) {
        if (threadIdx.x < st) red[threadIdx.x] += red[threadIdx.x + st];
        __syncthreads();
    }
    float inv = rsqrtf(red[0] / (float)NE + 1e-5f);
    for (int i = threadIdx.x; i < NE; i += 256)
        out[(size_t)t * NE + i] = row[i] * inv * w[i] + b[i];
}

// ---------------- fp32 -> fp16 convert ----------------
__global__ void f2h_kernel(const float* __restrict__ src, __half* __restrict__ dst, int n4) {
    int i = blockIdx.x * 256 + threadIdx.x;
    if (i >= n4) return;
    float4 v = ((const float4*)src)[i];
    __half2* dp = (__half2*)dst;
    dp[2 * i] = __floats2half2_rn(v.x, v.y);
    dp[2 * i + 1] = __floats2half2_rn(v.z, v.w);
}

// ---------------- weight padding kernels ----------------
__global__ void pad_xpw_kernel(const float* __restrict__ src, float* __restrict__ dst) {
    int i = blockIdx.x * 256 + threadIdx.x;
    if (i >= 128 * DI) return;
    int row = i / DI, col = i - row * DI;
    dst[i] = (row < 80) ? src[(size_t)row * DI + col] : 0.f;
}
__global__ void pad_dtw_kernel(const float* __restrict__ src, float* __restrict__ dst) {
    int i = blockIdx.x * 256 + threadIdx.x;
    if (i >= DI * 64) return;
    int row = i >> 6, col = i & 63;
    dst[i] = (col < DTR) ? src[(size_t)row * DTR + col] : 0.f;
}

// ======================================================================================
// fp16 tensor-core GEMM (m16n8k16, fp32 accumulate):
//   C[M,N] = A[M,K] @ B[N,K]^T  (+Res)
// CTA 128 x 256, 8 warps (2x4) of 64 x 64, BK=32, double-buffered cp.async,
// LDSM.x4 b16 fragment loads. Requires M%128==0, N%256==0, K%32==0.
// smem rows = 40 halfs (80B): ldmatrix quad = 5r mod 8 -> conflict-free.
// ======================================================================================
#define HSA (128 * 40)
#define HSB (256 * 40)
#define HSMEM_BYTES ((2 * HSA + 2 * HSB) * 2)

__global__ __launch_bounds__(256, 1) void gemm_mma_h(
    const __half* __restrict__ A, const __half* __restrict__ B,
    float* __restrict__ C, const float* __restrict__ Res,
    int M, int N, int K, int lda, int ldb, int ldc) {
    extern __shared__ char smemc[];
    __half* As = (__half*)smemc;          // [2][128][40]
    __half* Bs = As + 2 * HSA;            // [2][256][40]

    const int tid = threadIdx.x, wid = tid >> 5, lane = tid & 31;
    const int wm = wid >> 2, wn = wid & 3;
    const int bm = blockIdx.x * 128, bn = blockIdx.y * 256;
    const int NC = K >> 5;
    const int r = lane >> 2, cq = lane & 3;
    const int rowin = lane & 7, tsel = lane >> 3;

    float acc[4][8][4];
#pragma unroll
    for (int i = 0; i < 4; i++)
#pragma unroll
        for (int j = 0; j < 8; j++)
#pragma unroll
            for (int q = 0; q < 4; q++) acc[i][j][q] = 0.f;

    const int srow = tid >> 2, schunk = (tid & 3) * 8;   // 64 rows / iter, 4x8-half chunks

    auto stage = [&](int c, int b) {
        int k0 = c * 32;
        __half* sa = As + b * HSA;
        __half* sb = Bs + b * HSB;
#pragma unroll
        for (int i = 0; i < 2; i++) {
            int rr = srow + i * 64;
            cp16(smem_u32(sa + rr * 40 + schunk), A + (size_t)(bm + rr) * lda + k0 + schunk);
        }
#pragma unroll
        for (int i = 0; i < 4; i++) {
            int rr = srow + i * 64;
            cp16(smem_u32(sb + rr * 40 + schunk), B + (size_t)(bn + rr) * ldb + k0 + schunk);
        }
        cp_commit();
    };

    // ldmatrix per-thread offsets (halfs)
    // A m16k16 tile: t0-7 rows0-7 klo, t8-15 rows8-15 klo, t16-23 rows0-7 khi, t24-31 rows8-15 khi
    const int a_off = (wm * 64 + rowin + (tsel & 1) * 8) * 40 + (tsel >> 1) * 8;
    // B n8x2/k16: t0-7 n-tile j klo, t8-15 j khi, t16-23 j+1 klo, t24-31 j+1 khi
    const int b_off = (wn * 64 + rowin + (tsel >> 1) * 8) * 40 + (tsel & 1) * 8;

    stage(0, 0);
    for (int c = 0; c < NC; c++) {
        int buf = c & 1;
        if (c + 1 < NC) {
            stage(c + 1, buf ^ 1);
            asm volatile("cp.async.wait_group 1;" ::: "memory");
        } else {
            asm volatile("cp.async.wait_group 0;" ::: "memory");
        }
        __syncthreads();

        const uint32_t abase = smem_u32(As + buf * HSA + a_off);
        const uint32_t bbase = smem_u32(Bs + buf * HSB + b_off);
#pragma unroll
        for (int ks = 0; ks < 2; ks++) {               // two k16 steps per 32-chunk
            uint32_t af[4][4];
#pragma unroll
            for (int i = 0; i < 4; i++)
                LDSM4(af[i][0], af[i][1], af[i][2], af[i][3],
                      abase + (uint32_t)(i * 16 * 40 + ks * 16) * 2u);
            uint32_t bf[8][2];
#pragma unroll
            for (int jp = 0; jp < 4; jp++)
                LDSM4(bf[2 * jp][0], bf[2 * jp][1], bf[2 * jp + 1][0], bf[2 * jp + 1][1],
                      bbase + (uint32_t)(jp * 16 * 40 + ks * 16) * 2u);
#pragma unroll
            for (int i = 0; i < 4; i++)
#pragma unroll
                for (int j = 0; j < 8; j++)
                    asm volatile(
                        "mma.sync.aligned.m16n8k16.row.col.f32.f16.f16.f32 "
                        "{%0,%1,%2,%3}, {%4,%5,%6,%7}, {%8,%9}, {%0,%1,%2,%3};"
                        : "+f"(acc[i][j][0]), "+f"(acc[i][j][1]),
                          "+f"(acc[i][j][2]), "+f"(acc[i][j][3])
                        : "r"(af[i][0]), "r"(af[i][1]), "r"(af[i][2]), "r"(af[i][3]),
                          "r"(bf[j][0]), "r"(bf[j][1]));
        }
        __syncthreads();
    }

    // epilogue
#pragma unroll
    for (int i = 0; i < 4; i++) {
        int r0 = bm + wm * 64 + i * 16 + r;
#pragma unroll
        for (int j = 0; j < 8; j++) {
            int c0 = bn + wn * 64 + j * 8 + cq * 2;
            float v00 = acc[i][j][0], v01 = acc[i][j][1];
            float v10 = acc[i][j][2], v11 = acc[i][j][3];
            if (Res) {
                float2 p0 = *(const float2*)&Res[(size_t)r0 * ldc + c0];
                float2 p1 = *(const float2*)&Res[(size_t)(r0 + 8) * ldc + c0];
                v00 += p0.x; v01 += p0.y;
                v10 += p1.x; v11 += p1.y;
            }
            *(float2*)&C[(size_t)r0 * ldc + c0] = make_float2(v00, v01);
            *(float2*)&C[(size_t)(r0 + 8) * ldc + c0] = make_float2(v10, v11);
        }
    }
}

// ======================================================================================
// tf32 GEMM (kept for the small scan-feeding GEMMs): C = A @ B^T (+bias/softplus)
// ======================================================================================
template <int NT>
__global__ __launch_bounds__(256, 1) void gemm_mma(
    const float* __restrict__ A, const float* __restrict__ B,
    float* __restrict__ C, const float* __restrict__ Res, const float* __restrict__ bias,
    int M, int N, int K, int lda, int ldb, int ldc, int act) {
    constexpr int JT = NT / 32;
    constexpr int SA = 128 * 36;
    constexpr int SB = NT * 36;
    extern __shared__ float smem[];
    float* As = smem;
    float* Bs = smem + 2 * SA;

    const int tid = threadIdx.x, wid = tid >> 5, lane = tid & 31;
    const int wm = wid >> 2, wn = wid & 3;
    const int bm = blockIdx.x * 128, bn = blockIdx.y * NT;
    const int NC = K >> 5;
    const int r = lane >> 2, cq = lane & 3;
    const int rowin = lane & 7, tsel = lane >> 3;

    float acc[4][JT][4];
#pragma unroll
    for (int i = 0; i < 4; i++)
#pragma unroll
        for (int j = 0; j < JT; j++)
#pragma unroll
            for (int q = 0; q < 4; q++) acc[i][j][q] = 0.f;

    const int srow = tid >> 3, scol = (tid & 7) * 4;

    auto stage = [&](int c, int b) {
        int k0 = c * 32;
        float* sa = As + b * SA;
        float* sb = Bs + b * SB;
#pragma unroll
        for (int i = 0; i < 4; i++) {
            int rr = srow + i * 32;
            cp16(smem_u32(sa + rr * 36 + scol), A + (size_t)(bm + rr) * lda + k0 + scol);
        }
#pragma unroll
        for (int i = 0; i < NT / 32; i++) {
            int rr = srow + i * 32;
            cp16(smem_u32(sb + rr * 36 + scol), B + (size_t)(bn + rr) * ldb + k0 + scol);
        }
        cp_commit();
    };

    const int a_off = (wm * 64 + rowin + (tsel & 1) * 8) * 36 + (tsel >> 1) * 4;
    const int b_off = (wn * (NT / 4) + rowin + (tsel >> 1) * 8) * 36 + (tsel & 1) * 4;

    stage(0, 0);
    for (int c = 0; c < NC; c++) {
        int buf = c & 1;
        if (c + 1 < NC) {
            stage(c + 1, buf ^ 1);
            asm volatile("cp.async.wait_group 1;" ::: "memory");
        } else {
            asm volatile("cp.async.wait_group 0;" ::: "memory");
        }
        __syncthreads();

        const uint32_t abase = smem_u32(As + buf * SA + a_off);
        const uint32_t bbase = smem_u32(Bs + buf * SB + b_off);
#pragma unroll
        for (int ks = 0; ks < 4; ks++) {
            uint32_t af[4][4];
#pragma unroll
            for (int i = 0; i < 4; i++) {
                LDSM4(af[i][0], af[i][1], af[i][2], af[i][3],
                      abase + (uint32_t)(i * 16 * 36 + ks * 8) * 4u);
                af[i][0] = f2tf(af[i][0]); af[i][1] = f2tf(af[i][1]);
                af[i][2] = f2tf(af[i][2]); af[i][3] = f2tf(af[i][3]);
            }
            uint32_t bf[JT][2];
#pragma unroll
            for (int jp = 0; jp < JT / 2; jp++) {
                LDSM4(bf[2 * jp][0], bf[2 * jp][1], bf[2 * jp + 1][0], bf[2 * jp + 1][1],
                      bbase + (uint32_t)(jp * 16 * 36 + ks * 8) * 4u);
                bf[2 * jp][0] = f2tf(bf[2 * jp][0]);
                bf[2 * jp][1] = f2tf(bf[2 * jp][1]);
                bf[2 * jp + 1][0] = f2tf(bf[2 * jp + 1][0]);
                bf[2 * jp + 1][1] = f2tf(bf[2 * jp + 1][1]);
            }
#pragma unroll
            for (int i = 0; i < 4; i++)
#pragma unroll
                for (int j = 0; j < JT; j++)
                    asm volatile(
                        "mma.sync.aligned.m16n8k8.row.col.f32.tf32.tf32.f32 "
                        "{%0,%1,%2,%3}, {%4,%5,%6,%7}, {%8,%9}, {%0,%1,%2,%3};"
                        : "+f"(acc[i][j][0]), "+f"(acc[i][j][1]),
                          "+f"(acc[i][j][2]), "+f"(acc[i][j][3])
                        : "r"(af[i][0]), "r"(af[i][1]), "r"(af[i][2]), "r"(af[i][3]),
                          "r"(bf[j][0]), "r"(bf[j][1]));
        }
        __syncthreads();
    }

#pragma unroll
    for (int i = 0; i < 4; i++) {
        int r0 = bm + wm * 64 + i * 16 + r;
#pragma unroll
        for (int j = 0; j < JT; j++) {
            int c0 = bn + wn * (NT / 4) + j * 8 + cq * 2;
            float v00 = acc[i][j][0], v01 = acc[i][j][1];
            float v10 = acc[i][j][2], v11 = acc[i][j][3];
            if (bias) {
                float b0 = bias[c0], b1 = bias[c0 + 1];
                v00 += b0; v01 += b1; v10 += b0; v11 += b1;
            }
            if (act) {
                v00 = softplus_f(v00); v01 = softplus_f(v01);
                v10 = softplus_f(v10); v11 = softplus_f(v11);
            }
            if (Res) {
                float2 p0 = *(const float2*)&Res[(size_t)r0 * ldc + c0];
                float2 p1 = *(const float2*)&Res[(size_t)(r0 + 8) * ldc + c0];
                v00 += p0.x; v01 += p0.y;
                v10 += p1.x; v11 += p1.y;
            }
            *(float2*)&C[(size_t)r0 * ldc + c0] = make_float2(v00, v01);
            *(float2*)&C[(size_t)(r0 + 8) * ldc + c0] = make_float2(v10, v11);
        }
    }
}

#define SMEM_NT(NT) ((2 * 128 * 36 + 2 * (NT) * 36) * 4)

// ---------------- depthwise causal conv (d_conv=4) + bias + silu ----------------
__global__ void conv_silu_kernel(const float* __restrict__ xr, const float* __restrict__ cw,
                                 const float* __restrict__ cb, float* __restrict__ xc) {
    int i = blockIdx.x * 256 + threadIdx.x;
    if (i >= L * DI) return;
    int t = i / DI, d = i - t * DI;
    float acc = cb[d];
#pragma unroll
    for (int j = 0; j < 4; j++) {
        int ts = t - 3 + j;
        if (ts >= 0) acc = fmaf(cw[d * 4 + j], xr[(size_t)ts * (2 * DI) + d], acc);
    }
    xc[i] = sigmoid_mul(acc);
}

// ---------------- chunked selective scan ----------------
__global__ __launch_bounds__(128) void scan_phase1(
    const float* __restrict__ delta, const float* __restrict__ u,
    const float* __restrict__ xdbl, const float* __restrict__ A_log,
    float* __restrict__ fin, float* __restrict__ prod) {
    int p = blockIdx.y;
    int d = blockIdx.x * 128 + threadIdx.x;
    __shared__ float Bs[CH][DS];
    for (int i = threadIdx.x; i < CH * DS; i += 128) {
        int tt = i >> 4, n = i & 15;
        Bs[tt][n] = xdbl[(size_t)(p * CH + tt) * XPAD + 48 + n];
    }
    __syncthreads();
    float Aa[DS], x[DS], pa[DS];
#pragma unroll
    for (int n = 0; n < DS; n++) {
        Aa[n] = -__expf(A_log[(size_t)d * DS + n]);
        x[n] = 0.f;
        pa[n] = 1.f;
    }
    for (int tt = 0; tt < CH; tt++) {
        int t = p * CH + tt;
        float dl = delta[(size_t)t * DI + d];
        float uu = u[(size_t)t * DI + d];
        float du = dl * uu;
#pragma unroll
        for (int n = 0; n < DS; n++) {
            float e = __expf(dl * Aa[n]);
            x[n] = fmaf(e, x[n], du * Bs[tt][n]);
            pa[n] *= e;
        }
    }
    size_t base = (size_t)p * DI * DS + (size_t)d * DS;
#pragma unroll
    for (int n = 0; n < DS; n++) { fin[base + n] = x[n]; prod[base + n] = pa[n]; }
}

__global__ void scan_combine(const float* __restrict__ fin, const float* __restrict__ prod,
                             float* __restrict__ init) {
    int i = blockIdx.x * 256 + threadIdx.x;
    if (i >= DI * DS) return;
    float s = 0.f;
#pragma unroll 4
    for (int p = 0; p < NCHUNK; p++) {
        size_t idx = (size_t)p * DI * DS + i;
        init[idx] = s;
        s = fmaf(prod[idx], s, fin[idx]);
    }
}

__global__ __launch_bounds__(128) void scan_phase2(
    const float* __restrict__ delta, const float* __restrict__ u,
    const float* __restrict__ xdbl, const float* __restrict__ A_log,
    const float* __restrict__ init, const float* __restrict__ Dp,
    const float* __restrict__ xr, float* __restrict__ yout) {
    int p = blockIdx.y;
    int d = blockIdx.x * 128 + threadIdx.x;
    __shared__ float Bs[CH][DS];
    __shared__ float Cs[CH][DS];
    for (int i = threadIdx.x; i < CH * DS; i += 128) {
        int tt = i >> 4, n = i & 15;
        size_t row = (size_t)(p * CH + tt) * XPAD;
        Bs[tt][n] = xdbl[row + 48 + n];
        Cs[tt][n] = xdbl[row + 64 + n];
    }
    __syncthreads();
    float Aa[DS], x[DS];
    size_t base = (size_t)p * DI * DS + (size_t)d * DS;
#pragma unroll
    for (int n = 0; n < DS; n++) {
        Aa[n] = -__expf(A_log[(size_t)d * DS + n]);
        x[n] = init[base + n];
    }
    float Dd = Dp[d];
    for (int tt = 0; tt < CH; tt++) {
        int t = p * CH + tt;
        float dl = delta[(size_t)t * DI + d];
        float uu = u[(size_t)t * DI + d];
        float du = dl * uu;
        float y0 = 0.f, y1 = 0.f, y2 = 0.f, y3 = 0.f;
#pragma unroll
        for (int n = 0; n < DS; n++) {
            float e = __expf(dl * Aa[n]);
            x[n] = fmaf(e, x[n], du * Bs[tt][n]);
            float pr = x[n] * Cs[tt][n];
            if ((n & 3) == 0) y0 += pr;
            else if ((n & 3) == 1) y1 += pr;
            else if ((n & 3) == 2) y2 += pr;
            else y3 += pr;
        }
        float y = (y0 + y1) + (y2 + y3) + uu * Dd;
        float r = xr[(size_t)t * (2 * DI) + DI + d];
        yout[(size_t)t * DI + d] = y * sigmoid_mul(r);
    }
}

// ---------------- host orchestration ----------------
template <int NT>
static void launch_mma(const float* A, const float* B, float* C,
                       const float* Res, const float* bias,
                       int M, int N, int K, int lda, int ldb, int ldc, int act) {
    dim3 grid(M / 128, N / NT);
    gemm_mma<NT><<<grid, 256, SMEM_NT(NT)>>>(A, B, C, Res, bias, M, N, K, lda, ldb, ldc, act);
}
static void launch_mma_h(const __half* A, const __half* B, float* C, const float* Res,
                         int M, int N, int K, int lda, int ldb, int ldc) {
    dim3 grid(M / 128, N / 256);
    gemm_mma_h<<<grid, 256, HSMEM_BYTES>>>(A, B, C, Res, M, N, K, lda, ldb, ldc);
}
static void launch_f2h(const float* src, __half* dst, int n) {
    int n4 = n / 4;
    f2h_kernel<<<(n4 + 255) / 256, 256>>>(src, dst, n4);
}

extern "C" void kernel_launch(void* const* d_in, const int* in_sizes, int n_in,
                              void* d_out, int out_size) {
    const int*   tokens = (const int*)d_in[0];
    const float* E      = (const float*)d_in[1];
    const float* in_w   = (const float*)d_in[2];
    const float* conv_w = (const float*)d_in[3];
    const float* conv_b = (const float*)d_in[4];
    const float* xp_w   = (const float*)d_in[5];
    const float* dt_w   = (const float*)d_in[6];
    const float* dt_b   = (const float*)d_in[7];
    const float* A_log  = (const float*)d_in[8];
    const float* Dp     = (const float*)d_in[9];
    const float* out_w  = (const float*)d_in[10];
    const float* nw     = (const float*)d_in[11];
    const float* nb     = (const float*)d_in[12];
    const float* nfw    = (const float*)d_in[13];
    const float* nfb    = (const float*)d_in[14];
    float* logits = (float*)d_out;

    float *h, *xn, *xr, *xc, *xdbl, *delta, *y, *fin, *prod, *init, *xpwp, *dtwp;
    __half *ah, *wh;
    cudaGetSymbolAddress((void**)&h, g_h);
    cudaGetSymbolAddress((void**)&xn, g_xn);
    cudaGetSymbolAddress((void**)&xr, g_xr);
    cudaGetSymbolAddress((void**)&xc, g_xc);
    cudaGetSymbolAddress((void**)&xdbl, g_xdbl);
    cudaGetSymbolAddress((void**)&delta, g_delta);
    cudaGetSymbolAddress((void**)&y, g_y);
    cudaGetSymbolAddress((void**)&fin, g_fin);
    cudaGetSymbolAddress((void**)&prod, g_prod);
    cudaGetSymbolAddress((void**)&init, g_init);
    cudaGetSymbolAddress((void**)&xpwp, g_xpw_pad);
    cudaGetSymbolAddress((void**)&dtwp, g_dtw_pad);
    cudaGetSymbolAddress((void**)&ah, g_ah);
    cudaGetSymbolAddress((void**)&wh, g_wh);

    cudaFuncSetAttribute(gemm_mma<256>, cudaFuncAttributeMaxDynamicSharedMemorySize, SMEM_NT(256));
    cudaFuncSetAttribute(gemm_mma<128>, cudaFuncAttributeMaxDynamicSharedMemorySize, SMEM_NT(128));
    cudaFuncSetAttribute(gemm_mma_h, cudaFuncAttributeMaxDynamicSharedMemorySize, HSMEM_BYTES);

    embed_kernel<<<(L * NE + 255) / 256, 256>>>(tokens, E, h);

    for (int l = 0; l < 2; l++) {
        const float* l_inw  = in_w  + (size_t)l * (2 * DI) * NE;
        const float* l_cw   = conv_w + (size_t)l * DI * 4;
        const float* l_cb   = conv_b + (size_t)l * DI;
        const float* l_xpw  = xp_w  + (size_t)l * 80 * DI;
        const float* l_dtw  = dt_w  + (size_t)l * DI * DTR;
        const float* l_dtb  = dt_b  + (size_t)l * DI;
        const float* l_alog = A_log + (size_t)l * DI * DS;
        const float* l_dp   = Dp    + (size_t)l * DI;
        const float* l_outw = out_w + (size_t)l * NE * DI;

        pad_xpw_kernel<<<(128 * DI + 255) / 256, 256>>>(l_xpw, xpwp);
        pad_dtw_kernel<<<(DI * 64 + 255) / 256, 256>>>(l_dtw, dtwp);

        // xn = rmsnorm(h)
        rmsnorm_kernel<<<L, 256>>>(h, nw + l * NE, nb + l * NE, xn);
        // xr = xn @ in_proj^T  [L, 3072]  (fp16 tensor core)
        launch_f2h(xn, ah, L * NE);
        launch_f2h(l_inw, wh, 2 * DI * NE);
        launch_mma_h(ah, wh, xr, nullptr, L, 2 * DI, NE, NE, NE, 2 * DI);
        // xc = silu(depthwise causal conv(x) + b)
        conv_silu_kernel<<<(L * DI + 255) / 256, 256>>>(xr, l_cw, l_cb, xc);
        // xdbl = xc @ xpw_pad^T  [L, 128]  (tf32 — feeds scan)
        launch_mma<128>(xc, xpwp, xdbl, nullptr, nullptr, L, XPAD, DI, DI, DI, XPAD, 0);
        // delta = softplus(xdbl[:, :64] @ dtw_pad^T + dt_b)  [L, 1536]  (tf32 — feeds scan)
        launch_mma<256>(xdbl, dtwp, delta, nullptr, l_dtb, L, DI, 64, XPAD, 64, DI, 1);
        // chunked selective scan -> y
        scan_phase1<<<dim3(DI / 128, NCHUNK), 128>>>(delta, xc, xdbl, l_alog, fin, prod);
        scan_combine<<<(DI * DS + 255) / 256, 256>>>(fin, prod, init);
        scan_phase2<<<dim3(DI / 128, NCHUNK), 128>>>(delta, xc, xdbl, l_alog, init, l_dp, xr, y);
        // h = h + y @ out_proj^T  (fp16 tensor core, fused residual)
        launch_f2h(y, ah, L * DI);
        launch_f2h(l_outw, wh, NE * DI);
        launch_mma_h(ah, wh, h, h, L, NE, DI, DI, DI, NE);
    }

    // final norm + tied lm head (fp16 tensor core)
    rmsnorm_kernel<<<L, 256>>>(h, nfw, nfb, xn);
    launch_f2h(xn, ah, L * NE);
    launch_f2h(E, wh, 32000 * NE);
    launch_mma_h(ah, wh, logits, nullptr, L, 32000, NE, NE, NE, 32000);
}

// round 7
// speedup vs baseline: 5.2389x; 1.2224x over previous
#include <cuda_runtime.h>
#include <cuda_fp16.h>
#include <cstdint>
#include <cstddef>

#define L      2048
#define NE     768
#define DI     1536
#define DS     16
#define DTR    48
#define XPAD   128   // padded xdbl row stride
#define NCHUNK 64
#define CH     32    // NCHUNK*CH == L
#define KSPL   8     // split-K factor for the xdbl GEMM

// ---------------- scratch (static device globals; no allocation) ----------------
__device__ float g_h[L * NE];
__device__ float g_xr[L * 2 * DI];
__device__ float g_xc[L * DI];
__device__ float g_xdbl[L * XPAD];
__device__ float g_xdbl_part[KSPL * L * XPAD];
__device__ float g_delta[L * DI];
__device__ float g_fin[NCHUNK * DI * DS];
__device__ float g_prod[NCHUNK * DI * DS];
__device__ float g_init[NCHUNK * DI * DS];
__device__ float g_xpw_pad[128 * DI];     // x_proj_w padded 80 -> 128 rows
__device__ float g_dtw_pad[DI * 64];      // dt_proj_w padded 48 -> 64 cols
__device__ __half g_ah[L * DI];           // fp16 activations (max L*DI)
__device__ __half g_wh[32000 * NE];       // fp16 weights (max vocab*NE)

// ---------------- helpers ----------------
__device__ __forceinline__ uint32_t smem_u32(const void* p) {
    uint32_t a;
    asm("{ .reg .u64 t; cvta.to.shared.u64 t, %1; cvt.u32.u64 %0, t; }" : "=r"(a) : "l"(p));
    return a;
}
__device__ __forceinline__ void cp16(uint32_t s, const void* g) {
    asm volatile("cp.async.cg.shared.global [%0], [%1], 16;" :: "r"(s), "l"(g));
}
__device__ __forceinline__ void cp_commit() {
    asm volatile("cp.async.commit_group;" ::: "memory");
}
__device__ __forceinline__ uint32_t f2tf(uint32_t bits) {
    uint32_t r;
    asm("cvt.rna.tf32.f32 %0, %1;" : "=r"(r) : "f"(__uint_as_float(bits)));
    return r;
}
#define LDSM4(r0, r1, r2, r3, addr) \
    asm volatile("ldmatrix.sync.aligned.m8n8.x4.shared.b16 {%0,%1,%2,%3}, [%4];" \
                 : "=r"(r0), "=r"(r1), "=r"(r2), "=r"(r3) : "r"(addr))

__device__ __forceinline__ float sigmoid_mul(float x) { return x / (1.f + __expf(-x)); }
__device__ __forceinline__ float softplus_f(float x) {
    return fmaxf(x, 0.f) + log1pf(__expf(-fabsf(x)));
}

// ---------------- embedding ----------------
__global__ void embed_kernel(const int* __restrict__ tok, const float* __restrict__ E,
                             float* __restrict__ h) {
    int i = blockIdx.x * 256 + threadIdx.x;
    if (i < L * NE) {
        int t = i / NE, e = i - t * NE;
        h[i] = E[(size_t)tok[t] * NE + e];
    }
}

// ---------------- rmsnorm -> fp16 output (only fp16 GEMMs consume it) ----------------
__global__ void rmsnorm_h_kernel(const float* __restrict__ in, const float* __restrict__ w,
                                 const float* __restrict__ b, __half* __restrict__ out) {
    int t = blockIdx.x;
    const float* row = in + (size_t)t * NE;
    float s = 0.f;
    for (int i = threadIdx.x; i < NE; i += 256) { float v = row[i]; s += v * v; }
    __shared__ float red[256];
    red[threadIdx.x] = s;
    __syncthreads();
    for (int st = 128; st > 0; st >>= 1) {
        if (threadIdx.x < st) red[threadIdx.x] += red[threadIdx.x + st];
        __syncthreads();
    }
    float inv = rsqrtf(red[0] / (float)NE + 1e-5f);
    for (int i = threadIdx.x; i < NE; i += 256)
        out[(size_t)t * NE + i] = __float2half(row[i] * inv * w[i] + b[i]);
}

// ---------------- fp32 -> fp16 convert (weights) ----------------
__global__ void f2h_kernel(const float* __restrict__ src, __half* __restrict__ dst, int n4) {
    int i = blockIdx.x * 256 + threadIdx.x;
    if (i >= n4) return;
    float4 v = ((const float4*)src)[i];
    __half2* dp = (__half2*)dst;
    dp[2 * i] = __floats2half2_rn(v.x, v.y);
    dp[2 * i + 1] = __floats2half2_rn(v.z, v.w);
}

// ---------------- weight padding kernels ----------------
__global__ void pad_xpw_kernel(const float* __restrict__ src, float* __restrict__ dst) {
    int i = blockIdx.x * 256 + threadIdx.x;
    if (i >= 128 * DI) return;
    int row = i / DI, col = i - row * DI;
    dst[i] = (row < 80) ? src[(size_t)row * DI + col] : 0.f;
}
__global__ void pad_dtw_kernel(const float* __restrict__ src, float* __restrict__ dst) {
    int i = blockIdx.x * 256 + threadIdx.x;
    if (i >= DI * 64) return;
    int row = i >> 6, col = i & 63;
    dst[i] = (col < DTR) ? src[(size_t)row * DTR + col] : 0.f;
}

// ---------------- split-K reduction ----------------
__global__ void reduce_k_kernel(const float* __restrict__ part, float* __restrict__ out, int n) {
    int i = blockIdx.x * 256 + threadIdx.x;
    if (i >= n) return;
    float s = 0.f;
#pragma unroll
    for (int z = 0; z < KSPL; z++) s += part[(size_t)z * n + i];
    out[i] = s;
}

// ======================================================================================
// fp16 tensor-core GEMM (m16n8k16, fp32 accumulate), 3-stage pipeline:
//   C[M,N] = A[M,K] @ B[N,K]^T  (+Res)
// CTA 128 x 256, 8 warps (2x4) of 64 x 64, BK=32, triple-buffered cp.async,
// one __syncthreads per chunk, LDSM.x4 b16 fragment loads.
// Requires M%128==0, N%256==0, K%32==0. smem rows = 40 halfs -> ldmatrix conflict-free.
// ======================================================================================
#define HSA (128 * 40)
#define HSB (256 * 40)
#define HSTAGES 3
#define HSMEM_BYTES (HSTAGES * (HSA + HSB) * 2)

__global__ __launch_bounds__(256, 1) void gemm_mma_h(
    const __half* __restrict__ A, const __half* __restrict__ B,
    float* __restrict__ C, const float* __restrict__ Res,
    int M, int N, int K, int lda, int ldb, int ldc) {
    extern __shared__ char smemc[];
    __half* As = (__half*)smemc;          // [3][128][40]
    __half* Bs = As + HSTAGES * HSA;      // [3][256][40]

    const int tid = threadIdx.x, wid = tid >> 5, lane = tid & 31;
    const int wm = wid >> 2, wn = wid & 3;
    const int bm = blockIdx.x * 128, bn = blockIdx.y * 256;
    const int NC = K >> 5;
    const int r = lane >> 2, cq = lane & 3;
    const int rowin = lane & 7, tsel = lane >> 3;

    float acc[4][8][4];
#pragma unroll
    for (int i = 0; i < 4; i++)
#pragma unroll
        for (int j = 0; j < 8; j++)
#pragma unroll
            for (int q = 0; q < 4; q++) acc[i][j][q] = 0.f;

    const int srow = tid >> 2, schunk = (tid & 3) * 8;   // 64 rows / iter, 4x8-half chunks

    auto stage = [&](int c, int b) {
        int k0 = c * 32;
        __half* sa = As + b * HSA;
        __half* sb = Bs + b * HSB;
#pragma unroll
        for (int i = 0; i < 2; i++) {
            int rr = srow + i * 64;
            cp16(smem_u32(sa + rr * 40 + schunk), A + (size_t)(bm + rr) * lda + k0 + schunk);
        }
#pragma unroll
        for (int i = 0; i < 4; i++) {
            int rr = srow + i * 64;
            cp16(smem_u32(sb + rr * 40 + schunk), B + (size_t)(bn + rr) * ldb + k0 + schunk);
        }
        cp_commit();
    };

    // ldmatrix per-thread offsets (halfs)
    const int a_off = (wm * 64 + rowin + (tsel & 1) * 8) * 40 + (tsel >> 1) * 8;
    const int b_off = (wn * 64 + rowin + (tsel >> 1) * 8) * 40 + (tsel & 1) * 8;

    stage(0, 0);
    if (NC > 1) stage(1, 1);
    int buf = 0;
    for (int c = 0; c < NC; c++) {
        if (c + 1 < NC) {
            asm volatile("cp.async.wait_group 1;" ::: "memory");
        } else {
            asm volatile("cp.async.wait_group 0;" ::: "memory");
        }
        __syncthreads();

        const uint32_t abase = smem_u32(As + buf * HSA + a_off);
        const uint32_t bbase = smem_u32(Bs + buf * HSB + b_off);
#pragma unroll
        for (int ks = 0; ks < 2; ks++) {               // two k16 steps per 32-chunk
            uint32_t af[4][4];
#pragma unroll
            for (int i = 0; i < 4; i++)
                LDSM4(af[i][0], af[i][1], af[i][2], af[i][3],
                      abase + (uint32_t)(i * 16 * 40 + ks * 16) * 2u);
            uint32_t bf[8][2];
#pragma unroll
            for (int jp = 0; jp < 4; jp++)
                LDSM4(bf[2 * jp][0], bf[2 * jp][1], bf[2 * jp + 1][0], bf[2 * jp + 1][1],
                      bbase + (uint32_t)(jp * 16 * 40 + ks * 16) * 2u);
#pragma unroll
            for (int i = 0; i < 4; i++)
#pragma unroll
                for (int j = 0; j < 8; j++)
                    asm volatile(
                        "mma.sync.aligned.m16n8k16.row.col.f32.f16.f16.f32 "
                        "{%0,%1,%2,%3}, {%4,%5,%6,%7}, {%8,%9}, {%0,%1,%2,%3};"
                        : "+f"(acc[i][j][0]), "+f"(acc[i][j][1]),
                          "+f"(acc[i][j][2]), "+f"(acc[i][j][3])
                        : "r"(af[i][0]), "r"(af[i][1]), "r"(af[i][2]), "r"(af[i][3]),
                          "r"(bf[j][0]), "r"(bf[j][1]));
        }
        if (c + 2 < NC) {
            int nb = buf + 2; if (nb >= HSTAGES) nb -= HSTAGES;
            stage(c + 2, nb);
        }
        if (++buf == HSTAGES) buf = 0;
    }

    // epilogue
#pragma unroll
    for (int i = 0; i < 4; i++) {
        int r0 = bm + wm * 64 + i * 16 + r;
#pragma unroll
        for (int j = 0; j < 8; j++) {
            int c0 = bn + wn * 64 + j * 8 + cq * 2;
            float v00 = acc[i][j][0], v01 = acc[i][j][1];
            float v10 = acc[i][j][2], v11 = acc[i][j][3];
            if (Res) {
                float2 p0 = *(const float2*)&Res[(size_t)r0 * ldc + c0];
                float2 p1 = *(const float2*)&Res[(size_t)(r0 + 8) * ldc + c0];
                v00 += p0.x; v01 += p0.y;
                v10 += p1.x; v11 += p1.y;
            }
            *(float2*)&C[(size_t)r0 * ldc + c0] = make_float2(v00, v01);
            *(float2*)&C[(size_t)(r0 + 8) * ldc + c0] = make_float2(v10, v11);
        }
    }
}

// ======================================================================================
// tf32 GEMM (scan-feeding path; supports split-K via gridDim.z):
//   Cz = A[:, z*K:(z+1)*K] @ B[:, z*K:(z+1)*K]^T  (+bias/softplus/Res)
// ======================================================================================
template <int NT>
__global__ __launch_bounds__(256, 1) void gemm_mma(
    const float* __restrict__ A, const float* __restrict__ B,
    float* __restrict__ C, const float* __restrict__ Res, const float* __restrict__ bias,
    int M, int N, int K, int lda, int ldb, int ldc, int act, size_t czstride) {
    constexpr int JT = NT / 32;
    constexpr int SA = 128 * 36;
    constexpr int SB = NT * 36;
    extern __shared__ float smem[];
    float* As = smem;
    float* Bs = smem + 2 * SA;

    {
        int zz = blockIdx.z;
        A += (size_t)zz * K;
        B += (size_t)zz * K;
        C += (size_t)zz * czstride;
    }

    const int tid = threadIdx.x, wid = tid >> 5, lane = tid & 31;
    const int wm = wid >> 2, wn = wid & 3;
    const int bm = blockIdx.x * 128, bn = blockIdx.y * NT;
    const int NC = K >> 5;
    const int r = lane >> 2, cq = lane & 3;
    const int rowin = lane & 7, tsel = lane >> 3;

    float acc[4][JT][4];
#pragma unroll
    for (int i = 0; i < 4; i++)
#pragma unroll
        for (int j = 0; j < JT; j++)
#pragma unroll
            for (int q = 0; q < 4; q++) acc[i][j][q] = 0.f;

    const int srow = tid >> 3, scol = (tid & 7) * 4;

    auto stage = [&](int c, int b) {
        int k0 = c * 32;
        float* sa = As + b * SA;
        float* sb = Bs + b * SB;
#pragma unroll
        for (int i = 0; i < 4; i++) {
            int rr = srow + i * 32;
            cp16(smem_u32(sa + rr * 36 + scol), A + (size_t)(bm + rr) * lda + k0 + scol);
        }
#pragma unroll
        for (int i = 0; i < NT / 32; i++) {
            int rr = srow + i * 32;
            cp16(smem_u32(sb + rr * 36 + scol), B + (size_t)(bn + rr) * ldb + k0 + scol);
        }
        cp_commit();
    };

    const int a_off = (wm * 64 + rowin + (tsel & 1) * 8) * 36 + (tsel >> 1) * 4;
    const int b_off = (wn * (NT / 4) + rowin + (tsel >> 1) * 8) * 36 + (tsel & 1) * 4;

    stage(0, 0);
    for (int c = 0; c < NC; c++) {
        int buf = c & 1;
        if (c + 1 < NC) {
            stage(c + 1, buf ^ 1);
            asm volatile("cp.async.wait_group 1;" ::: "memory");
        } else {
            asm volatile("cp.async.wait_group 0;" ::: "memory");
        }
        __syncthreads();

        const uint32_t abase = smem_u32(As + buf * SA + a_off);
        const uint32_t bbase = smem_u32(Bs + buf * SB + b_off);
#pragma unroll
        for (int ks = 0; ks < 4; ks++) {
            uint32_t af[4][4];
#pragma unroll
            for (int i = 0; i < 4; i++) {
                LDSM4(af[i][0], af[i][1], af[i][2], af[i][3],
                      abase + (uint32_t)(i * 16 * 36 + ks * 8) * 4u);
                af[i][0] = f2tf(af[i][0]); af[i][1] = f2tf(af[i][1]);
                af[i][2] = f2tf(af[i][2]); af[i][3] = f2tf(af[i][3]);
            }
            uint32_t bf[JT][2];
#pragma unroll
            for (int jp = 0; jp < JT / 2; jp++) {
                LDSM4(bf[2 * jp][0], bf[2 * jp][1], bf[2 * jp + 1][0], bf[2 * jp + 1][1],
                      bbase + (uint32_t)(jp * 16 * 36 + ks * 8) * 4u);
                bf[2 * jp][0] = f2tf(bf[2 * jp][0]);
                bf[2 * jp][1] = f2tf(bf[2 * jp][1]);
                bf[2 * jp + 1][0] = f2tf(bf[2 * jp + 1][0]);
                bf[2 * jp + 1][1] = f2tf(bf[2 * jp + 1][1]);
            }
#pragma unroll
            for (int i = 0; i < 4; i++)
#pragma unroll
                for (int j = 0; j < JT; j++)
                    asm volatile(
                        "mma.sync.aligned.m16n8k8.row.col.f32.tf32.tf32.f32 "
                        "{%0,%1,%2,%3}, {%4,%5,%6,%7}, {%8,%9}, {%0,%1,%2,%3};"
                        : "+f"(acc[i][j][0]), "+f"(acc[i][j][1]),
                          "+f"(acc[i][j][2]), "+f"(acc[i][j][3])
                        : "r"(af[i][0]), "r"(af[i][1]), "r"(af[i][2]), "r"(af[i][3]),
                          "r"(bf[j][0]), "r"(bf[j][1]));
        }
        __syncthreads();
    }

#pragma unroll
    for (int i = 0; i < 4; i++) {
        int r0 = bm + wm * 64 + i * 16 + r;
#pragma unroll
        for (int j = 0; j < JT; j++) {
            int c0 = bn + wn * (NT / 4) + j * 8 + cq * 2;
            float v00 = acc[i][j][0], v01 = acc[i][j][1];
            float v10 = acc[i][j][2], v11 = acc[i][j][3];
            if (bias) {
                float b0 = bias[c0], b1 = bias[c0 + 1];
                v00 += b0; v01 += b1; v10 += b0; v11 += b1;
            }
            if (act) {
                v00 = softplus_f(v00); v01 = softplus_f(v01);
                v10 = softplus_f(v10); v11 = softplus_f(v11);
            }
            if (Res) {
                float2 p0 = *(const float2*)&Res[(size_t)r0 * ldc + c0];
                float2 p1 = *(const float2*)&Res[(size_t)(r0 + 8) * ldc + c0];
                v00 += p0.x; v01 += p0.y;
                v10 += p1.x; v11 += p1.y;
            }
            *(float2*)&C[(size_t)r0 * ldc + c0] = make_float2(v00, v01);
            *(float2*)&C[(size_t)(r0 + 8) * ldc + c0] = make_float2(v10, v11);
        }
    }
}

#define SMEM_NT(NT) ((2 * 128 * 36 + 2 * (NT) * 36) * 4)

// ---------------- depthwise causal conv (d_conv=4) + bias + silu ----------------
__global__ void conv_silu_kernel(const float* __restrict__ xr, const float* __restrict__ cw,
                                 const float* __restrict__ cb, float* __restrict__ xc) {
    int i = blockIdx.x * 256 + threadIdx.x;
    if (i >= L * DI) return;
    int t = i / DI, d = i - t * DI;
    float acc = cb[d];
#pragma unroll
    for (int j = 0; j < 4; j++) {
        int ts = t - 3 + j;
        if (ts >= 0) acc = fmaf(cw[d * 4 + j], xr[(size_t)ts * (2 * DI) + d], acc);
    }
    xc[i] = sigmoid_mul(acc);
}

// ---------------- chunked selective scan ----------------
__global__ __launch_bounds__(128) void scan_phase1(
    const float* __restrict__ delta, const float* __restrict__ u,
    const float* __restrict__ xdbl, const float* __restrict__ A_log,
    float* __restrict__ fin, float* __restrict__ prod) {
    int p = blockIdx.y;
    int d = blockIdx.x * 128 + threadIdx.x;
    __shared__ float Bs[CH][DS];
    for (int i = threadIdx.x; i < CH * DS; i += 128) {
        int tt = i >> 4, n = i & 15;
        Bs[tt][n] = xdbl[(size_t)(p * CH + tt) * XPAD + 48 + n];
    }
    __syncthreads();
    float Aa[DS], x[DS], pa[DS];
#pragma unroll
    for (int n = 0; n < DS; n++) {
        Aa[n] = -__expf(A_log[(size_t)d * DS + n]);
        x[n] = 0.f;
        pa[n] = 1.f;
    }
    for (int tt = 0; tt < CH; tt++) {
        int t = p * CH + tt;
        float dl = delta[(size_t)t * DI + d];
        float uu = u[(size_t)t * DI + d];
        float du = dl * uu;
#pragma unroll
        for (int n = 0; n < DS; n++) {
            float e = __expf(dl * Aa[n]);
            x[n] = fmaf(e, x[n], du * Bs[tt][n]);
            pa[n] *= e;
        }
    }
    size_t base = (size_t)p * DI * DS + (size_t)d * DS;
#pragma unroll
    for (int n = 0; n < DS; n++) { fin[base + n] = x[n]; prod[base + n] = pa[n]; }
}

__global__ void scan_combine(const float* __restrict__ fin, const float* __restrict__ prod,
                             float* __restrict__ init) {
    int i = blockIdx.x * 256 + threadIdx.x;
    if (i >= DI * DS) return;
    float s = 0.f;
#pragma unroll 4
    for (int p = 0; p < NCHUNK; p++) {
        size_t idx = (size_t)p * DI * DS + i;
        init[idx] = s;
        s = fmaf(prod[idx], s, fin[idx]);
    }
}

// phase 2 emits fp16 y directly (only the fp16 out_proj GEMM consumes it)
__global__ __launch_bounds__(128) void scan_phase2(
    const float* __restrict__ delta, const float* __restrict__ u,
    const float* __restrict__ xdbl, const float* __restrict__ A_log,
    const float* __restrict__ init, const float* __restrict__ Dp,
    const float* __restrict__ xr, __half* __restrict__ yout) {
    int p = blockIdx.y;
    int d = blockIdx.x * 128 + threadIdx.x;
    __shared__ float Bs[CH][DS];
    __shared__ float Cs[CH][DS];
    for (int i = threadIdx.x; i < CH * DS; i += 128) {
        int tt = i >> 4, n = i & 15;
        size_t row = (size_t)(p * CH + tt) * XPAD;
        Bs[tt][n] = xdbl[row + 48 + n];
        Cs[tt][n] = xdbl[row + 64 + n];
    }
    __syncthreads();
    float Aa[DS], x[DS];
    size_t base = (size_t)p * DI * DS + (size_t)d * DS;
#pragma unroll
    for (int n = 0; n < DS; n++) {
        Aa[n] = -__expf(A_log[(size_t)d * DS + n]);
        x[n] = init[base + n];
    }
    float Dd = Dp[d];
    for (int tt = 0; tt < CH; tt++) {
        int t = p * CH + tt;
        float dl = delta[(size_t)t * DI + d];
        float uu = u[(size_t)t * DI + d];
        float du = dl * uu;
        float y0 = 0.f, y1 = 0.f, y2 = 0.f, y3 = 0.f;
#pragma unroll
        for (int n = 0; n < DS; n++) {
            float e = __expf(dl * Aa[n]);
            x[n] = fmaf(e, x[n], du * Bs[tt][n]);
            float pr = x[n] * Cs[tt][n];
            if ((n & 3) == 0) y0 += pr;
            else if ((n & 3) == 1) y1 += pr;
            else if ((n & 3) == 2) y2 += pr;
            else y3 += pr;
        }
        float y = (y0 + y1) + (y2 + y3) + uu * Dd;
        float r = xr[(size_t)t * (2 * DI) + DI + d];
        yout[(size_t)t * DI + d] = __float2half(y * sigmoid_mul(r));
    }
}

// ---------------- host orchestration ----------------
template <int NT>
static void launch_mma(const float* A, const float* B, float* C,
                       const float* Res, const float* bias,
                       int M, int N, int K, int lda, int ldb, int ldc, int act,
                       int zsplit = 1, size_t czstride = 0) {
    dim3 grid(M / 128, N / NT, zsplit);
    gemm_mma<NT><<<grid, 256, SMEM_NT(NT)>>>(A, B, C, Res, bias, M, N, K, lda, ldb, ldc,
                                             act, czstride);
}
static void launch_mma_h(const __half* A, const __half* B, float* C, const float* Res,
                         int M, int N, int K, int lda, int ldb, int ldc) {
    dim3 grid(M / 128, N / 256);
    gemm_mma_h<<<grid, 256, HSMEM_BYTES>>>(A, B, C, Res, M, N, K, lda, ldb, ldc);
}
static void launch_f2h(const float* src, __half* dst, int n) {
    int n4 = n / 4;
    f2h_kernel<<<(n4 + 255) / 256, 256>>>(src, dst, n4);
}

extern "C" void kernel_launch(void* const* d_in, const int* in_sizes, int n_in,
                              void* d_out, int out_size) {
    const int*   tokens = (const int*)d_in[0];
    const float* E      = (const float*)d_in[1];
    const float* in_w   = (const float*)d_in[2];
    const float* conv_w = (const float*)d_in[3];
    const float* conv_b = (const float*)d_in[4];
    const float* xp_w   = (const float*)d_in[5];
    const float* dt_w   = (const float*)d_in[6];
    const float* dt_b   = (const float*)d_in[7];
    const float* A_log  = (const float*)d_in[8];
    const float* Dp     = (const float*)d_in[9];
    const float* out_w  = (const float*)d_in[10];
    const float* nw     = (const float*)d_in[11];
    const float* nb     = (const float*)d_in[12];
    const float* nfw    = (const float*)d_in[13];
    const float* nfb    = (const float*)d_in[14];
    float* logits = (float*)d_out;

    float *h, *xr, *xc, *xdbl, *xdblp, *delta, *fin, *prod, *init, *xpwp, *dtwp;
    __half *ah, *wh;
    cudaGetSymbolAddress((void**)&h, g_h);
    cudaGetSymbolAddress((void**)&xr, g_xr);
    cudaGetSymbolAddress((void**)&xc, g_xc);
    cudaGetSymbolAddress((void**)&xdbl, g_xdbl);
    cudaGetSymbolAddress((void**)&xdblp, g_xdbl_part);
    cudaGetSymbolAddress((void**)&delta, g_delta);
    cudaGetSymbolAddress((void**)&fin, g_fin);
    cudaGetSymbolAddress((void**)&prod, g_prod);
    cudaGetSymbolAddress((void**)&init, g_init);
    cudaGetSymbolAddress((void**)&xpwp, g_xpw_pad);
    cudaGetSymbolAddress((void**)&dtwp, g_dtw_pad);
    cudaGetSymbolAddress((void**)&ah, g_ah);
    cudaGetSymbolAddress((void**)&wh, g_wh);

    cudaFuncSetAttribute(gemm_mma<256>, cudaFuncAttributeMaxDynamicSharedMemorySize, SMEM_NT(256));
    cudaFuncSetAttribute(gemm_mma<128>, cudaFuncAttributeMaxDynamicSharedMemorySize, SMEM_NT(128));
    cudaFuncSetAttribute(gemm_mma_h, cudaFuncAttributeMaxDynamicSharedMemorySize, HSMEM_BYTES);

    embed_kernel<<<(L * NE + 255) / 256, 256>>>(tokens, E, h);

    for (int l = 0; l < 2; l++) {
        const float* l_inw  = in_w  + (size_t)l * (2 * DI) * NE;
        const float* l_cw   = conv_w + (size_t)l * DI * 4;
        const float* l_cb   = conv_b + (size_t)l * DI;
        const float* l_xpw  = xp_w  + (size_t)l * 80 * DI;
        const float* l_dtw  = dt_w  + (size_t)l * DI * DTR;
        const float* l_dtb  = dt_b  + (size_t)l * DI;
        const float* l_alog = A_log + (size_t)l * DI * DS;
        const float* l_dp   = Dp    + (size_t)l * DI;
        const float* l_outw = out_w + (size_t)l * NE * DI;

        pad_xpw_kernel<<<(128 * DI + 255) / 256, 256>>>(l_xpw, xpwp);
        pad_dtw_kernel<<<(DI * 64 + 255) / 256, 256>>>(l_dtw, dtwp);

        // ah = fp16 rmsnorm(h)
        rmsnorm_h_kernel<<<L, 256>>>(h, nw + l * NE, nb + l * NE, ah);
        // xr = ah @ in_proj^T  [L, 3072]  (fp16 tensor core)
        launch_f2h(l_inw, wh, 2 * DI * NE);
        launch_mma_h(ah, wh, xr, nullptr, L, 2 * DI, NE, NE, NE, 2 * DI);
        // xc = silu(depthwise causal conv(x) + b)
        conv_silu_kernel<<<(L * DI + 255) / 256, 256>>>(xr, l_cw, l_cb, xc);
        // xdbl = xc @ xpw_pad^T  [L, 128]  (tf32, split-K x8 + deterministic reduce)
        launch_mma<128>(xc, xpwp, xdblp, nullptr, nullptr, L, XPAD, DI / KSPL,
                        DI, DI, XPAD, 0, KSPL, (size_t)L * XPAD);
        reduce_k_kernel<<<(L * XPAD + 255) / 256, 256>>>(xdblp, xdbl, L * XPAD);
        // delta = softplus(xdbl[:, :64] @ dtw_pad^T + dt_b)  [L, 1536]  (tf32)
        launch_mma<256>(xdbl, dtwp, delta, nullptr, l_dtb, L, DI, 64, XPAD, 64, DI, 1);
        // chunked selective scan -> y (fp16, written to ah)
        scan_phase1<<<dim3(DI / 128, NCHUNK), 128>>>(delta, xc, xdbl, l_alog, fin, prod);
        scan_combine<<<(DI * DS + 255) / 256, 256>>>(fin, prod, init);
        scan_phase2<<<dim3(DI / 128, NCHUNK), 128>>>(delta, xc, xdbl, l_alog, init, l_dp, xr, ah);
        // h = h + y @ out_proj^T  (fp16 tensor core, fused residual)
        launch_f2h(l_outw, wh, NE * DI);
        launch_mma_h(ah, wh, h, h, L, NE, DI, DI, DI, NE);
    }

    // final norm + tied lm head (fp16 tensor core)
    rmsnorm_h_kernel<<<L, 256>>>(h, nfw, nfb, ah);
    launch_f2h(E, wh, 32000 * NE);
    launch_mma_h(ah, wh, logits, nullptr, L, 32000, NE, NE, NE, 32000);
}

// round 8
// speedup vs baseline: 5.6084x; 1.0705x over previous
#include <cuda_runtime.h>
#include <cuda_fp16.h>
#include <cstdint>
#include <cstddef>

#define L      2048
#define NE     768
#define DI     1536
#define DS     16
#define DTR    48
#define XPAD   128   // padded xdbl row stride
#define NCHUNK 64
#define CH     32    // NCHUNK*CH == L
#define KSPL   8     // split-K factor for the xdbl GEMM
#define KSPO   4     // split-K factor for the out_proj GEMM

// ---------------- scratch (static device globals; no allocation) ----------------
__device__ float g_h[L * NE];
__device__ float g_xr[L * 2 * DI];
__device__ float g_xc[L * DI];
__device__ float g_xdbl[L * XPAD];
__device__ float g_xdbl_part[KSPL * L * XPAD];
__device__ float g_opart[KSPO * L * NE];
__device__ float g_delta[L * DI];
__device__ float g_fin[NCHUNK * DI * DS];
__device__ float g_prod[NCHUNK * DI * DS];
__device__ float g_init[NCHUNK * DI * DS];
__device__ float g_xpw_pad[128 * DI];     // x_proj_w padded 80 -> 128 rows
__device__ float g_dtw_pad[DI * 64];      // dt_proj_w padded 48 -> 64 cols
__device__ __half g_ah[L * DI];           // fp16 activations (max L*DI)
__device__ __half g_wh[32000 * NE];       // fp16 weights (max vocab*NE)

// ---------------- helpers ----------------
__device__ __forceinline__ uint32_t smem_u32(const void* p) {
    uint32_t a;
    asm("{ .reg .u64 t; cvta.to.shared.u64 t, %1; cvt.u32.u64 %0, t; }" : "=r"(a) : "l"(p));
    return a;
}
__device__ __forceinline__ void cp16(uint32_t s, const void* g) {
    asm volatile("cp.async.cg.shared.global [%0], [%1], 16;" :: "r"(s), "l"(g));
}
__device__ __forceinline__ void cp_commit() {
    asm volatile("cp.async.commit_group;" ::: "memory");
}
__device__ __forceinline__ uint32_t f2tf(uint32_t bits) {
    uint32_t r;
    asm("cvt.rna.tf32.f32 %0, %1;" : "=r"(r) : "f"(__uint_as_float(bits)));
    return r;
}
#define LDSM4(r0, r1, r2, r3, addr) \
    asm volatile("ldmatrix.sync.aligned.m8n8.x4.shared.b16 {%0,%1,%2,%3}, [%4];" \
                 : "=r"(r0), "=r"(r1), "=r"(r2), "=r"(r3) : "r"(addr))

__device__ __forceinline__ float sigmoid_mul(float x) { return x / (1.f + __expf(-x)); }
__device__ __forceinline__ float softplus_f(float x) {
    return fmaxf(x, 0.f) + log1pf(__expf(-fabsf(x)));
}

// ---------------- embedding ----------------
__global__ void embed_kernel(const int* __restrict__ tok, const float* __restrict__ E,
                             float* __restrict__ h) {
    int i = blockIdx.x * 256 + threadIdx.x;
    if (i < L * NE) {
        int t = i / NE, e = i - t * NE;
        h[i] = E[(size_t)tok[t] * NE + e];
    }
}

// ---------------- rmsnorm -> fp16, single pass, register-cached ----------------
__global__ __launch_bounds__(256) void rmsnorm_h_kernel(
    const float* __restrict__ in, const float* __restrict__ w,
    const float* __restrict__ b, __half* __restrict__ out) {
    int t = blockIdx.x, tid = threadIdx.x;
    const float* row = in + (size_t)t * NE;
    float v0 = row[tid], v1 = row[tid + 256], v2 = row[tid + 512];
    float s = v0 * v0 + v1 * v1 + v2 * v2;
#pragma unroll
    for (int o = 16; o > 0; o >>= 1) s += __shfl_xor_sync(0xffffffffu, s, o);
    __shared__ float ws[8];
    if ((tid & 31) == 0) ws[tid >> 5] = s;
    __syncthreads();
    float tot = ws[0] + ws[1] + ws[2] + ws[3] + ws[4] + ws[5] + ws[6] + ws[7];
    float inv = rsqrtf(tot / (float)NE + 1e-5f);
    __half* orow = out + (size_t)t * NE;
    orow[tid]       = __float2half(v0 * inv * w[tid] + b[tid]);
    orow[tid + 256] = __float2half(v1 * inv * w[tid + 256] + b[tid + 256]);
    orow[tid + 512] = __float2half(v2 * inv * w[tid + 512] + b[tid + 512]);
}

// ---------------- fp32 -> fp16 convert (weights) ----------------
__global__ void f2h_kernel(const float* __restrict__ src, __half* __restrict__ dst, int n4) {
    int i = blockIdx.x * 256 + threadIdx.x;
    if (i >= n4) return;
    float4 v = ((const float4*)src)[i];
    __half2* dp = (__half2*)dst;
    dp[2 * i] = __floats2half2_rn(v.x, v.y);
    dp[2 * i + 1] = __floats2half2_rn(v.z, v.w);
}

// ---------------- weight padding kernels ----------------
__global__ void pad_xpw_kernel(const float* __restrict__ src, float* __restrict__ dst) {
    int i = blockIdx.x * 256 + threadIdx.x;
    if (i >= 128 * DI) return;
    int row = i / DI, col = i - row * DI;
    dst[i] = (row < 80) ? src[(size_t)row * DI + col] : 0.f;
}
__global__ void pad_dtw_kernel(const float* __restrict__ src, float* __restrict__ dst) {
    int i = blockIdx.x * 256 + threadIdx.x;
    if (i >= DI * 64) return;
    int row = i >> 6, col = i & 63;
    dst[i] = (col < DTR) ? src[(size_t)row * DTR + col] : 0.f;
}

// ---------------- split-K reductions ----------------
__global__ void reduce_k_kernel(const float* __restrict__ part, float* __restrict__ out, int n) {
    int i = blockIdx.x * 256 + threadIdx.x;
    if (i >= n) return;
    float s = 0.f;
#pragma unroll
    for (int z = 0; z < KSPL; z++) s += part[(size_t)z * n + i];
    out[i] = s;
}
// h[i] += sum_z part[z][i]  (fused residual for split-K out_proj)
__global__ void reduce_res_kernel(const float* __restrict__ part, float* __restrict__ h, int n4) {
    int i = blockIdx.x * 256 + threadIdx.x;
    if (i >= n4) return;
    float4 a = ((const float4*)h)[i];
#pragma unroll
    for (int z = 0; z < KSPO; z++) {
        float4 p = ((const float4*)(part + (size_t)z * (n4 * 4)))[i];
        a.x += p.x; a.y += p.y; a.z += p.z; a.w += p.w;
    }
    ((float4*)h)[i] = a;
}

// ======================================================================================
// fp16 tensor-core GEMM (m16n8k16, fp32 accumulate), 3-stage pipeline, templated NT:
//   C[M,N] = A[M,K] @ B[N,K]^T  (+Res)   (split-K via gridDim.z: C += z*czstride)
// CTA 128 x NT, 8 warps (2x4) of 64 x NT/4, BK=32, triple-buffered cp.async,
// one __syncthreads per chunk, LDSM.x4 b16 fragment loads.
// Requires M%128==0, N%NT==0, K%32==0. smem rows = 40 halfs -> ldmatrix conflict-free.
// ======================================================================================
#define HSA (128 * 40)
#define HSTAGES 3
#define HSMEM_NT(NT) (HSTAGES * (HSA + (NT) * 40) * 2)

template <int NT>
__global__ __launch_bounds__(256, 1) void gemm_mma_h(
    const __half* __restrict__ A, const __half* __restrict__ B,
    float* __restrict__ C, const float* __restrict__ Res,
    int M, int N, int K, int lda, int ldb, int ldc, size_t czstride) {
    constexpr int JT = NT / 32;
    constexpr int HSB = NT * 40;
    extern __shared__ char smemc[];
    __half* As = (__half*)smemc;          // [3][128][40]
    __half* Bs = As + HSTAGES * HSA;      // [3][NT][40]

    {
        int zz = blockIdx.z;
        A += (size_t)zz * K;
        B += (size_t)zz * K;
        C += (size_t)zz * czstride;
    }

    const int tid = threadIdx.x, wid = tid >> 5, lane = tid & 31;
    const int wm = wid >> 2, wn = wid & 3;
    const int bm = blockIdx.x * 128, bn = blockIdx.y * NT;
    const int NC = K >> 5;
    const int r = lane >> 2, cq = lane & 3;
    const int rowin = lane & 7, tsel = lane >> 3;

    float acc[4][JT][4];
#pragma unroll
    for (int i = 0; i < 4; i++)
#pragma unroll
        for (int j = 0; j < JT; j++)
#pragma unroll
            for (int q = 0; q < 4; q++) acc[i][j][q] = 0.f;

    const int srow = tid >> 2, schunk = (tid & 3) * 8;   // 64 rows / iter

    auto stage = [&](int c, int b) {
        int k0 = c * 32;
        __half* sa = As + b * HSA;
        __half* sb = Bs + b * HSB;
#pragma unroll
        for (int i = 0; i < 2; i++) {
            int rr = srow + i * 64;
            cp16(smem_u32(sa + rr * 40 + schunk), A + (size_t)(bm + rr) * lda + k0 + schunk);
        }
#pragma unroll
        for (int i = 0; i < NT / 64; i++) {
            int rr = srow + i * 64;
            cp16(smem_u32(sb + rr * 40 + schunk), B + (size_t)(bn + rr) * ldb + k0 + schunk);
        }
        cp_commit();
    };

    // ldmatrix per-thread offsets (halfs)
    const int a_off = (wm * 64 + rowin + (tsel & 1) * 8) * 40 + (tsel >> 1) * 8;
    const int b_off = (wn * (NT / 4) + rowin + (tsel >> 1) * 8) * 40 + (tsel & 1) * 8;

    stage(0, 0);
    if (NC > 1) stage(1, 1);
    int buf = 0;
    for (int c = 0; c < NC; c++) {
        if (c + 1 < NC) {
            asm volatile("cp.async.wait_group 1;" ::: "memory");
        } else {
            asm volatile("cp.async.wait_group 0;" ::: "memory");
        }
        __syncthreads();

        const uint32_t abase = smem_u32(As + buf * HSA + a_off);
        const uint32_t bbase = smem_u32(Bs + buf * HSB + b_off);
#pragma unroll
        for (int ks = 0; ks < 2; ks++) {               // two k16 steps per 32-chunk
            uint32_t af[4][4];
#pragma unroll
            for (int i = 0; i < 4; i++)
                LDSM4(af[i][0], af[i][1], af[i][2], af[i][3],
                      abase + (uint32_t)(i * 16 * 40 + ks * 16) * 2u);
            uint32_t bf[JT][2];
#pragma unroll
            for (int jp = 0; jp < JT / 2; jp++)
                LDSM4(bf[2 * jp][0], bf[2 * jp][1], bf[2 * jp + 1][0], bf[2 * jp + 1][1],
                      bbase + (uint32_t)(jp * 16 * 40 + ks * 16) * 2u);
#pragma unroll
            for (int i = 0; i < 4; i++)
#pragma unroll
                for (int j = 0; j < JT; j++)
                    asm volatile(
                        "mma.sync.aligned.m16n8k16.row.col.f32.f16.f16.f32 "
                        "{%0,%1,%2,%3}, {%4,%5,%6,%7}, {%8,%9}, {%0,%1,%2,%3};"
                        : "+f"(acc[i][j][0]), "+f"(acc[i][j][1]),
                          "+f"(acc[i][j][2]), "+f"(acc[i][j][3])
                        : "r"(af[i][0]), "r"(af[i][1]), "r"(af[i][2]), "r"(af[i][3]),
                          "r"(bf[j][0]), "r"(bf[j][1]));
        }
        if (c + 2 < NC) {
            int nb = buf + 2; if (nb >= HSTAGES) nb -= HSTAGES;
            stage(c + 2, nb);
        }
        if (++buf == HSTAGES) buf = 0;
    }

    // epilogue
#pragma unroll
    for (int i = 0; i < 4; i++) {
        int r0 = bm + wm * 64 + i * 16 + r;
#pragma unroll
        for (int j = 0; j < JT; j++) {
            int c0 = bn + wn * (NT / 4) + j * 8 + cq * 2;
            float v00 = acc[i][j][0], v01 = acc[i][j][1];
            float v10 = acc[i][j][2], v11 = acc[i][j][3];
            if (Res) {
                float2 p0 = *(const float2*)&Res[(size_t)r0 * ldc + c0];
                float2 p1 = *(const float2*)&Res[(size_t)(r0 + 8) * ldc + c0];
                v00 += p0.x; v01 += p0.y;
                v10 += p1.x; v11 += p1.y;
            }
            *(float2*)&C[(size_t)r0 * ldc + c0] = make_float2(v00, v01);
            *(float2*)&C[(size_t)(r0 + 8) * ldc + c0] = make_float2(v10, v11);
        }
    }
}

// ======================================================================================
// tf32 GEMM (scan-feeding path; supports split-K via gridDim.z)
// ======================================================================================
template <int NT>
__global__ __launch_bounds__(256, 1) void gemm_mma(
    const float* __restrict__ A, const float* __restrict__ B,
    float* __restrict__ C, const float* __restrict__ Res, const float* __restrict__ bias,
    int M, int N, int K, int lda, int ldb, int ldc, int act, size_t czstride) {
    constexpr int JT = NT / 32;
    constexpr int SA = 128 * 36;
    constexpr int SB = NT * 36;
    extern __shared__ float smem[];
    float* As = smem;
    float* Bs = smem + 2 * SA;

    {
        int zz = blockIdx.z;
        A += (size_t)zz * K;
        B += (size_t)zz * K;
        C += (size_t)zz * czstride;
    }

    const int tid = threadIdx.x, wid = tid >> 5, lane = tid & 31;
    const int wm = wid >> 2, wn = wid & 3;
    const int bm = blockIdx.x * 128, bn = blockIdx.y * NT;
    const int NC = K >> 5;
    const int r = lane >> 2, cq = lane & 3;
    const int rowin = lane & 7, tsel = lane >> 3;

    float acc[4][JT][4];
#pragma unroll
    for (int i = 0; i < 4; i++)
#pragma unroll
        for (int j = 0; j < JT; j++)
#pragma unroll
            for (int q = 0; q < 4; q++) acc[i][j][q] = 0.f;

    const int srow = tid >> 3, scol = (tid & 7) * 4;

    auto stage = [&](int c, int b) {
        int k0 = c * 32;
        float* sa = As + b * SA;
        float* sb = Bs + b * SB;
#pragma unroll
        for (int i = 0; i < 4; i++) {
            int rr = srow + i * 32;
            cp16(smem_u32(sa + rr * 36 + scol), A + (size_t)(bm + rr) * lda + k0 + scol);
        }
#pragma unroll
        for (int i = 0; i < NT / 32; i++) {
            int rr = srow + i * 32;
            cp16(smem_u32(sb + rr * 36 + scol), B + (size_t)(bn + rr) * ldb + k0 + scol);
        }
        cp_commit();
    };

    const int a_off = (wm * 64 + rowin + (tsel & 1) * 8) * 36 + (tsel >> 1) * 4;
    const int b_off = (wn * (NT / 4) + rowin + (tsel >> 1) * 8) * 36 + (tsel & 1) * 4;

    stage(0, 0);
    for (int c = 0; c < NC; c++) {
        int buf = c & 1;
        if (c + 1 < NC) {
            stage(c + 1, buf ^ 1);
            asm volatile("cp.async.wait_group 1;" ::: "memory");
        } else {
            asm volatile("cp.async.wait_group 0;" ::: "memory");
        }
        __syncthreads();

        const uint32_t abase = smem_u32(As + buf * SA + a_off);
        const uint32_t bbase = smem_u32(Bs + buf * SB + b_off);
#pragma unroll
        for (int ks = 0; ks < 4; ks++) {
            uint32_t af[4][4];
#pragma unroll
            for (int i = 0; i < 4; i++) {
                LDSM4(af[i][0], af[i][1], af[i][2], af[i][3],
                      abase + (uint32_t)(i * 16 * 36 + ks * 8) * 4u);
                af[i][0] = f2tf(af[i][0]); af[i][1] = f2tf(af[i][1]);
                af[i][2] = f2tf(af[i][2]); af[i][3] = f2tf(af[i][3]);
            }
            uint32_t bf[JT][2];
#pragma unroll
            for (int jp = 0; jp < JT / 2; jp++) {
                LDSM4(bf[2 * jp][0], bf[2 * jp][1], bf[2 * jp + 1][0], bf[2 * jp + 1][1],
                      bbase + (uint32_t)(jp * 16 * 36 + ks * 8) * 4u);
                bf[2 * jp][0] = f2tf(bf[2 * jp][0]);
                bf[2 * jp][1] = f2tf(bf[2 * jp][1]);
                bf[2 * jp + 1][0] = f2tf(bf[2 * jp + 1][0]);
                bf[2 * jp + 1][1] = f2tf(bf[2 * jp + 1][1]);
            }
#pragma unroll
            for (int i = 0; i < 4; i++)
#pragma unroll
                for (int j = 0; j < JT; j++)
                    asm volatile(
                        "mma.sync.aligned.m16n8k8.row.col.f32.tf32.tf32.f32 "
                        "{%0,%1,%2,%3}, {%4,%5,%6,%7}, {%8,%9}, {%0,%1,%2,%3};"
                        : "+f"(acc[i][j][0]), "+f"(acc[i][j][1]),
                          "+f"(acc[i][j][2]), "+f"(acc[i][j][3])
                        : "r"(af[i][0]), "r"(af[i][1]), "r"(af[i][2]), "r"(af[i][3]),
                          "r"(bf[j][0]), "r"(bf[j][1]));
        }
        __syncthreads();
    }

#pragma unroll
    for (int i = 0; i < 4; i++) {
        int r0 = bm + wm * 64 + i * 16 + r;
#pragma unroll
        for (int j = 0; j < JT; j++) {
            int c0 = bn + wn * (NT / 4) + j * 8 + cq * 2;
            float v00 = acc[i][j][0], v01 = acc[i][j][1];
            float v10 = acc[i][j][2], v11 = acc[i][j][3];
            if (bias) {
                float b0 = bias[c0], b1 = bias[c0 + 1];
                v00 += b0; v01 += b1; v10 += b0; v11 += b1;
            }
            if (act) {
                v00 = softplus_f(v00); v01 = softplus_f(v01);
                v10 = softplus_f(v10); v11 = softplus_f(v11);
            }
            if (Res) {
                float2 p0 = *(const float2*)&Res[(size_t)r0 * ldc + c0];
                float2 p1 = *(const float2*)&Res[(size_t)(r0 + 8) * ldc + c0];
                v00 += p0.x; v01 += p0.y;
                v10 += p1.x; v11 += p1.y;
            }
            *(float2*)&C[(size_t)r0 * ldc + c0] = make_float2(v00, v01);
            *(float2*)&C[(size_t)(r0 + 8) * ldc + c0] = make_float2(v10, v11);
        }
    }
}

#define SMEM_NT(NT) ((2 * 128 * 36 + 2 * (NT) * 36) * 4)

// ---------------- depthwise causal conv + bias + silu, smem-tiled ----------------
#define CT 32
__global__ __launch_bounds__(256) void conv_silu_kernel(
    const float* __restrict__ xr, const float* __restrict__ cw,
    const float* __restrict__ cb, float* __restrict__ xc) {
    __shared__ float sx[CT + 3][256];
    int d = blockIdx.x * 256 + threadIdx.x;
    int t0 = blockIdx.y * CT;
#pragma unroll 5
    for (int rr = 0; rr < CT + 3; rr++) {
        int ts = t0 - 3 + rr;
        sx[rr][threadIdx.x] = (ts >= 0) ? xr[(size_t)ts * (2 * DI) + d] : 0.f;
    }
    __syncthreads();
    float w0 = cw[d * 4 + 0], w1 = cw[d * 4 + 1], w2 = cw[d * 4 + 2], w3 = cw[d * 4 + 3];
    float bb = cb[d];
#pragma unroll 8
    for (int tt = 0; tt < CT; tt++) {
        float acc = bb;
        acc = fmaf(w0, sx[tt][threadIdx.x], acc);
        acc = fmaf(w1, sx[tt + 1][threadIdx.x], acc);
        acc = fmaf(w2, sx[tt + 2][threadIdx.x], acc);
        acc = fmaf(w3, sx[tt + 3][threadIdx.x], acc);
        xc[(size_t)(t0 + tt) * DI + d] = sigmoid_mul(acc);
    }
}

// ---------------- chunked selective scan ----------------
__global__ __launch_bounds__(128) void scan_phase1(
    const float* __restrict__ delta, const float* __restrict__ u,
    const float* __restrict__ xdbl, const float* __restrict__ A_log,
    float* __restrict__ fin, float* __restrict__ prod) {
    int p = blockIdx.y;
    int d = blockIdx.x * 128 + threadIdx.x;
    __shared__ float Bs[CH][DS];
    for (int i = threadIdx.x; i < CH * DS; i += 128) {
        int tt = i >> 4, n = i & 15;
        Bs[tt][n] = xdbl[(size_t)(p * CH + tt) * XPAD + 48 + n];
    }
    __syncthreads();
    float Aa[DS], x[DS], pa[DS];
#pragma unroll
    for (int n = 0; n < DS; n++) {
        Aa[n] = -__expf(A_log[(size_t)d * DS + n]);
        x[n] = 0.f;
        pa[n] = 1.f;
    }
    for (int tt = 0; tt < CH; tt++) {
        int t = p * CH + tt;
        float dl = delta[(size_t)t * DI + d];
        float uu = u[(size_t)t * DI + d];
        float du = dl * uu;
#pragma unroll
        for (int n = 0; n < DS; n++) {
            float e = __expf(dl * Aa[n]);
            x[n] = fmaf(e, x[n], du * Bs[tt][n]);
            pa[n] *= e;
        }
    }
    size_t base = (size_t)p * DI * DS + (size_t)d * DS;
#pragma unroll
    for (int n = 0; n < DS; n++) { fin[base + n] = x[n]; prod[base + n] = pa[n]; }
}

__global__ void scan_combine(const float* __restrict__ fin, const float* __restrict__ prod,
                             float* __restrict__ init) {
    int i = blockIdx.x * 256 + threadIdx.x;
    if (i >= DI * DS) return;
    float s = 0.f;
#pragma unroll 4
    for (int p = 0; p < NCHUNK; p++) {
        size_t idx = (size_t)p * DI * DS + i;
        init[idx] = s;
        s = fmaf(prod[idx], s, fin[idx]);
    }
}

// phase 2 emits fp16 y directly (only the fp16 out_proj GEMM consumes it)
__global__ __launch_bounds__(128) void scan_phase2(
    const float* __restrict__ delta, const float* __restrict__ u,
    const float* __restrict__ xdbl, const float* __restrict__ A_log,
    const float* __restrict__ init, const float* __restrict__ Dp,
    const float* __restrict__ xr, __half* __restrict__ yout) {
    int p = blockIdx.y;
    int d = blockIdx.x * 128 + threadIdx.x;
    __shared__ float Bs[CH][DS];
    __shared__ float Cs[CH][DS];
    for (int i = threadIdx.x; i < CH * DS; i += 128) {
        int tt = i >> 4, n = i & 15;
        size_t row = (size_t)(p * CH + tt) * XPAD;
        Bs[tt][n] = xdbl[row + 48 + n];
        Cs[tt][n] = xdbl[row + 64 + n];
    }
    __syncthreads();
    float Aa[DS], x[DS];
    size_t base = (size_t)p * DI * DS + (size_t)d * DS;
#pragma unroll
    for (int n = 0; n < DS; n++) {
        Aa[n] = -__expf(A_log[(size_t)d * DS + n]);
        x[n] = init[base + n];
    }
    float Dd = Dp[d];
    for (int tt = 0; tt < CH; tt++) {
        int t = p * CH + tt;
        float dl = delta[(size_t)t * DI + d];
        float uu = u[(size_t)t * DI + d];
        float du = dl * uu;
        float y0 = 0.f, y1 = 0.f, y2 = 0.f, y3 = 0.f;
#pragma unroll
        for (int n = 0; n < DS; n++) {
            float e = __expf(dl * Aa[n]);
            x[n] = fmaf(e, x[n], du * Bs[tt][n]);
            float pr = x[n] * Cs[tt][n];
            if ((n & 3) == 0) y0 += pr;
            else if ((n & 3) == 1) y1 += pr;
            else if ((n & 3) == 2) y2 += pr;
            else y3 += pr;
        }
        float y = (y0 + y1) + (y2 + y3) + uu * Dd;
        float r = xr[(size_t)t * (2 * DI) + DI + d];
        yout[(size_t)t * DI + d] = __float2half(y * sigmoid_mul(r));
    }
}

// ---------------- host orchestration ----------------
template <int NT>
static void launch_mma(const float* A, const float* B, float* C,
                       const float* Res, const float* bias,
                       int M, int N, int K, int lda, int ldb, int ldc, int act,
                       int zsplit = 1, size_t czstride = 0) {
    dim3 grid(M / 128, N / NT, zsplit);
    gemm_mma<NT><<<grid, 256, SMEM_NT(NT)>>>(A, B, C, Res, bias, M, N, K, lda, ldb, ldc,
                                             act, czstride);
}
template <int NT>
static void launch_mma_h(const __half* A, const __half* B, float* C, const float* Res,
                         int M, int N, int K, int lda, int ldb, int ldc,
                         int zsplit = 1, size_t czstride = 0) {
    dim3 grid(M / 128, N / NT, zsplit);
    gemm_mma_h<NT><<<grid, 256, HSMEM_NT(NT)>>>(A, B, C, Res, M, N, K, lda, ldb, ldc, czstride);
}
static void launch_f2h(const float* src, __half* dst, int n) {
    int n4 = n / 4;
    f2h_kernel<<<(n4 + 255) / 256, 256>>>(src, dst, n4);
}

extern "C" void kernel_launch(void* const* d_in, const int* in_sizes, int n_in,
                              void* d_out, int out_size) {
    const int*   tokens = (const int*)d_in[0];
    const float* E      = (const float*)d_in[1];
    const float* in_w   = (const float*)d_in[2];
    const float* conv_w = (const float*)d_in[3];
    const float* conv_b = (const float*)d_in[4];
    const float* xp_w   = (const float*)d_in[5];
    const float* dt_w   = (const float*)d_in[6];
    const float* dt_b   = (const float*)d_in[7];
    const float* A_log  = (const float*)d_in[8];
    const float* Dp     = (const float*)d_in[9];
    const float* out_w  = (const float*)d_in[10];
    const float* nw     = (const float*)d_in[11];
    const float* nb     = (const float*)d_in[12];
    const float* nfw    = (const float*)d_in[13];
    const float* nfb    = (const float*)d_in[14];
    float* logits = (float*)d_out;

    float *h, *xr, *xc, *xdbl, *xdblp, *opart, *delta, *fin, *prod, *init, *xpwp, *dtwp;
    __half *ah, *wh;
    cudaGetSymbolAddress((void**)&h, g_h);
    cudaGetSymbolAddress((void**)&xr, g_xr);
    cudaGetSymbolAddress((void**)&xc, g_xc);
    cudaGetSymbolAddress((void**)&xdbl, g_xdbl);
    cudaGetSymbolAddress((void**)&xdblp, g_xdbl_part);
    cudaGetSymbolAddress((void**)&opart, g_opart);
    cudaGetSymbolAddress((void**)&delta, g_delta);
    cudaGetSymbolAddress((void**)&fin, g_fin);
    cudaGetSymbolAddress((void**)&prod, g_prod);
    cudaGetSymbolAddress((void**)&init, g_init);
    cudaGetSymbolAddress((void**)&xpwp, g_xpw_pad);
    cudaGetSymbolAddress((void**)&dtwp, g_dtw_pad);
    cudaGetSymbolAddress((void**)&ah, g_ah);
    cudaGetSymbolAddress((void**)&wh, g_wh);

    cudaFuncSetAttribute(gemm_mma<256>, cudaFuncAttributeMaxDynamicSharedMemorySize, SMEM_NT(256));
    cudaFuncSetAttribute(gemm_mma<128>, cudaFuncAttributeMaxDynamicSharedMemorySize, SMEM_NT(128));
    cudaFuncSetAttribute(gemm_mma_h<256>, cudaFuncAttributeMaxDynamicSharedMemorySize, HSMEM_NT(256));
    cudaFuncSetAttribute(gemm_mma_h<128>, cudaFuncAttributeMaxDynamicSharedMemorySize, HSMEM_NT(128));

    embed_kernel<<<(L * NE + 255) / 256, 256>>>(tokens, E, h);

    for (int l = 0; l < 2; l++) {
        const float* l_inw  = in_w  + (size_t)l * (2 * DI) * NE;
        const float* l_cw   = conv_w + (size_t)l * DI * 4;
        const float* l_cb   = conv_b + (size_t)l * DI;
        const float* l_xpw  = xp_w  + (size_t)l * 80 * DI;
        const float* l_dtw  = dt_w  + (size_t)l * DI * DTR;
        const float* l_dtb  = dt_b  + (size_t)l * DI;
        const float* l_alog = A_log + (size_t)l * DI * DS;
        const float* l_dp   = Dp    + (size_t)l * DI;
        const float* l_outw = out_w + (size_t)l * NE * DI;

        pad_xpw_kernel<<<(128 * DI + 255) / 256, 256>>>(l_xpw, xpwp);
        pad_dtw_kernel<<<(DI * 64 + 255) / 256, 256>>>(l_dtw, dtwp);

        // ah = fp16 rmsnorm(h)
        rmsnorm_h_kernel<<<L, 256>>>(h, nw + l * NE, nb + l * NE, ah);
        // xr = ah @ in_proj^T  [L, 3072]  (fp16, NT=128 for grid balance)
        launch_f2h(l_inw, wh, 2 * DI * NE);
        launch_mma_h<128>(ah, wh, xr, nullptr, L, 2 * DI, NE, NE, NE, 2 * DI);
        // xc = silu(depthwise causal conv(x) + b)   (smem-tiled)
        conv_silu_kernel<<<dim3(DI / 256, L / CT), 256>>>(xr, l_cw, l_cb, xc);
        // xdbl = xc @ xpw_pad^T  [L, 128]  (tf32, split-K x8 + deterministic reduce)
        launch_mma<128>(xc, xpwp, xdblp, nullptr, nullptr, L, XPAD, DI / KSPL,
                        DI, DI, XPAD, 0, KSPL, (size_t)L * XPAD);
        reduce_k_kernel<<<(L * XPAD + 255) / 256, 256>>>(xdblp, xdbl, L * XPAD);
        // delta = softplus(xdbl[:, :64] @ dtw_pad^T + dt_b)  [L, 1536]  (tf32)
        launch_mma<256>(xdbl, dtwp, delta, nullptr, l_dtb, L, DI, 64, XPAD, 64, DI, 1);
        // chunked selective scan -> y (fp16, written to ah)
        scan_phase1<<<dim3(DI / 128, NCHUNK), 128>>>(delta, xc, xdbl, l_alog, fin, prod);
        scan_combine<<<(DI * DS + 255) / 256, 256>>>(fin, prod, init);
        scan_phase2<<<dim3(DI / 128, NCHUNK), 128>>>(delta, xc, xdbl, l_alog, init, l_dp, xr, ah);
        // h = h + y @ out_proj^T  (fp16, NT=128 split-K x4 + fused residual reduce)
        launch_f2h(l_outw, wh, NE * DI);
        launch_mma_h<128>(ah, wh, opart, nullptr, L, NE, DI / KSPO, DI, DI, NE,
                          KSPO, (size_t)L * NE);
        reduce_res_kernel<<<(L * NE / 4 + 255) / 256, 256>>>(opart, h, L * NE / 4);
    }

    // final norm + tied lm head (fp16, NT=256)
    rmsnorm_h_kernel<<<L, 256>>>(h, nfw, nfb, ah);
    launch_f2h(E, wh, 32000 * NE);
    launch_mma_h<256>(ah, wh, logits, nullptr, L, 32000, NE, NE, NE, 32000);
}

// round 9
// speedup vs baseline: 5.9701x; 1.0645x over previous
#include <cuda_runtime.h>
#include <cuda_fp16.h>
#include <cstdint>
#include <cstddef>

#define L      2048
#define NE     768
#define DI     1536
#define DS     16
#define DTR    48
#define XPAD   128   // padded xdbl row stride
#define NCHUNK 64
#define CH     32    // NCHUNK*CH == L
#define KSPL   8     // split-K factor for the xdbl GEMM
#define KSPO   4     // split-K factor for the out_proj GEMM

// ---------------- scratch (static device globals; no allocation) ----------------
__device__ float g_h[L * NE];
__device__ float g_xr[L * 2 * DI];
__device__ float g_xc[L * DI];
__device__ float g_xdbl[L * XPAD];
__device__ float g_xdbl_part[KSPL * L * XPAD];
__device__ float g_opart[KSPO * L * NE];
__device__ float g_delta[L * DI];
__device__ float g_fin[NCHUNK * DI * DS];
__device__ float g_prod[NCHUNK * DI * DS];
__device__ float g_init[NCHUNK * DI * DS];
__device__ float g_xpw_pad[128 * DI];     // x_proj_w padded 80 -> 128 rows
__device__ float g_dtw_pad[DI * 64];      // dt_proj_w padded 48 -> 64 cols
__device__ __half g_ah[L * DI];           // fp16 activations (max L*DI)
__device__ __half g_wh[32000 * NE];       // fp16 weights (max vocab*NE)

// ---------------- helpers ----------------
__device__ __forceinline__ uint32_t smem_u32(const void* p) {
    uint32_t a;
    asm("{ .reg .u64 t; cvta.to.shared.u64 t, %1; cvt.u32.u64 %0, t; }" : "=r"(a) : "l"(p));
    return a;
}
__device__ __forceinline__ void cp16(uint32_t s, const void* g) {
    asm volatile("cp.async.cg.shared.global [%0], [%1], 16;" :: "r"(s), "l"(g));
}
__device__ __forceinline__ void cp_commit() {
    asm volatile("cp.async.commit_group;" ::: "memory");
}
__device__ __forceinline__ uint32_t f2tf(uint32_t bits) {
    uint32_t r;
    asm("cvt.rna.tf32.f32 %0, %1;" : "=r"(r) : "f"(__uint_as_float(bits)));
    return r;
}
#define LDSM4(r0, r1, r2, r3, addr) \
    asm volatile("ldmatrix.sync.aligned.m8n8.x4.shared.b16 {%0,%1,%2,%3}, [%4];" \
                 : "=r"(r0), "=r"(r1), "=r"(r2), "=r"(r3) : "r"(addr))

__device__ __forceinline__ float sigmoid_mul(float x) { return x / (1.f + __expf(-x)); }
__device__ __forceinline__ float softplus_f(float x) {
    return fmaxf(x, 0.f) + log1pf(__expf(-fabsf(x)));
}

// ---------------- embedding ----------------
__global__ void embed_kernel(const int* __restrict__ tok, const float* __restrict__ E,
                             float* __restrict__ h) {
    int i = blockIdx.x * 256 + threadIdx.x;
    if (i < L * NE) {
        int t = i / NE, e = i - t * NE;
        h[i] = E[(size_t)tok[t] * NE + e];
    }
}

// ---------------- rmsnorm -> fp16, single pass, register-cached ----------------
__global__ __launch_bounds__(256) void rmsnorm_h_kernel(
    const float* __restrict__ in, const float* __restrict__ w,
    const float* __restrict__ b, __half* __restrict__ out) {
    int t = blockIdx.x, tid = threadIdx.x;
    const float* row = in + (size_t)t * NE;
    float v0 = row[tid], v1 = row[tid + 256], v2 = row[tid + 512];
    float s = v0 * v0 + v1 * v1 + v2 * v2;
#pragma unroll
    for (int o = 16; o > 0; o >>= 1) s += __shfl_xor_sync(0xffffffffu, s, o);
    __shared__ float ws[8];
    if ((tid & 31) == 0) ws[tid >> 5] = s;
    __syncthreads();
    float tot = ws[0] + ws[1] + ws[2] + ws[3] + ws[4] + ws[5] + ws[6] + ws[7];
    float inv = rsqrtf(tot / (float)NE + 1e-5f);
    __half* orow = out + (size_t)t * NE;
    orow[tid]       = __float2half(v0 * inv * w[tid] + b[tid]);
    orow[tid + 256] = __float2half(v1 * inv * w[tid + 256] + b[tid + 256]);
    orow[tid + 512] = __float2half(v2 * inv * w[tid + 512] + b[tid + 512]);
}

// ---------------- fp32 -> fp16 convert (weights) ----------------
__global__ void f2h_kernel(const float* __restrict__ src, __half* __restrict__ dst, int n4) {
    int i = blockIdx.x * 256 + threadIdx.x;
    if (i >= n4) return;
    float4 v = ((const float4*)src)[i];
    __half2* dp = (__half2*)dst;
    dp[2 * i] = __floats2half2_rn(v.x, v.y);
    dp[2 * i + 1] = __floats2half2_rn(v.z, v.w);
}

// ---------------- weight padding kernels ----------------
__global__ void pad_xpw_kernel(const float* __restrict__ src, float* __restrict__ dst) {
    int i = blockIdx.x * 256 + threadIdx.x;
    if (i >= 128 * DI) return;
    int row = i / DI, col = i - row * DI;
    dst[i] = (row < 80) ? src[(size_t)row * DI + col] : 0.f;
}
__global__ void pad_dtw_kernel(const float* __restrict__ src, float* __restrict__ dst) {
    int i = blockIdx.x * 256 + threadIdx.x;
    if (i >= DI * 64) return;
    int row = i >> 6, col = i & 63;
    dst[i] = (col < DTR) ? src[(size_t)row * DTR + col] : 0.f;
}

// ---------------- split-K reductions ----------------
__global__ void reduce_k_kernel(const float* __restrict__ part, float* __restrict__ out, int n) {
    int i = blockIdx.x * 256 + threadIdx.x;
    if (i >= n) return;
    float s = 0.f;
#pragma unroll
    for (int z = 0; z < KSPL; z++) s += part[(size_t)z * n + i];
    out[i] = s;
}
// h[i] += sum_z part[z][i]  (fused residual for split-K out_proj)
__global__ void reduce_res_kernel(const float* __restrict__ part, float* __restrict__ h, int n4) {
    int i = blockIdx.x * 256 + threadIdx.x;
    if (i >= n4) return;
    float4 a = ((const float4*)h)[i];
#pragma unroll
    for (int z = 0; z < KSPO; z++) {
        float4 p = ((const float4*)(part + (size_t)z * ((size_t)n4 * 4)))[i];
        a.x += p.x; a.y += p.y; a.z += p.z; a.w += p.w;
    }
    ((float4*)h)[i] = a;
}

// ======================================================================================
// fp16 tensor-core GEMM (m16n8k16, fp32 accumulate), BK=64, 3-stage pipeline:
//   C[M,N] = A[M,K] @ B[N,K]^T  (+Res)   (split-K via gridDim.z: C += z*czstride)
// CTA 128 x NT, 8 warps (2x4) of 64 x NT/4, triple-buffered cp.async,
// one __syncthreads per 64-K chunk, LDSM.x4 b16 fragment loads.
// Requires M%128==0, N%NT==0, K%64==0.
// smem rows = 72 halfs: ldmatrix quad = (9r+q) mod 8 = (r+q) mod 8 -> conflict-free.
// ======================================================================================
#define HRS 72
#define HSA (128 * HRS)
#define HSTAGES 3
#define HSMEM_NT(NT) (HSTAGES * (HSA + (NT) * HRS) * 2)

template <int NT>
__global__ __launch_bounds__(256, 1) void gemm_mma_h(
    const __half* __restrict__ A, const __half* __restrict__ B,
    float* __restrict__ C, const float* __restrict__ Res,
    int M, int N, int K, int lda, int ldb, int ldc, size_t czstride) {
    constexpr int JT = NT / 32;
    constexpr int HSB = NT * HRS;
    extern __shared__ char smemc[];
    __half* As = (__half*)smemc;          // [3][128][72]
    __half* Bs = As + HSTAGES * HSA;      // [3][NT][72]

    {
        int zz = blockIdx.z;
        A += (size_t)zz * K;
        B += (size_t)zz * K;
        C += (size_t)zz * czstride;
    }

    const int tid = threadIdx.x, wid = tid >> 5, lane = tid & 31;
    const int wm = wid >> 2, wn = wid & 3;
    const int bm = blockIdx.x * 128, bn = blockIdx.y * NT;
    const int NC = K >> 6;
    const int r = lane >> 2, cq = lane & 3;
    const int rowin = lane & 7, tsel = lane >> 3;

    float acc[4][JT][4];
#pragma unroll
    for (int i = 0; i < 4; i++)
#pragma unroll
        for (int j = 0; j < JT; j++)
#pragma unroll
            for (int q = 0; q < 4; q++) acc[i][j][q] = 0.f;

    const int srow0 = tid >> 3, sj = (tid & 7) * 8;    // 32 rows / iter, 8x8-half chunks/row

    auto stage = [&](int c, int b) {
        int k0 = c * 64;
        __half* sa = As + b * HSA;
        __half* sb = Bs + b * HSB;
#pragma unroll
        for (int i = 0; i < 4; i++) {                   // A: 128 rows
            int rr = srow0 + i * 32;
            cp16(smem_u32(sa + rr * HRS + sj), A + (size_t)(bm + rr) * lda + k0 + sj);
        }
#pragma unroll
        for (int i = 0; i < NT / 32; i++) {             // B: NT rows
            int rr = srow0 + i * 32;
            cp16(smem_u32(sb + rr * HRS + sj), B + (size_t)(bn + rr) * ldb + k0 + sj);
        }
        cp_commit();
    };

    // ldmatrix per-thread offsets (halfs)
    const int a_off = (wm * 64 + rowin + (tsel & 1) * 8) * HRS + (tsel >> 1) * 8;
    const int b_off = (wn * (NT / 4) + rowin + (tsel >> 1) * 8) * HRS + (tsel & 1) * 8;

    stage(0, 0);
    if (NC > 1) stage(1, 1);
    int buf = 0;
    for (int c = 0; c < NC; c++) {
        if (c + 1 < NC) {
            asm volatile("cp.async.wait_group 1;" ::: "memory");
        } else {
            asm volatile("cp.async.wait_group 0;" ::: "memory");
        }
        __syncthreads();

        const uint32_t abase = smem_u32(As + buf * HSA + a_off);
        const uint32_t bbase = smem_u32(Bs + buf * HSB + b_off);
#pragma unroll
        for (int ks = 0; ks < 4; ks++) {               // four k16 steps per 64-chunk
            uint32_t af[4][4];
#pragma unroll
            for (int i = 0; i < 4; i++)
                LDSM4(af[i][0], af[i][1], af[i][2], af[i][3],
                      abase + (uint32_t)(i * 16 * HRS + ks * 16) * 2u);
            uint32_t bf[JT][2];
#pragma unroll
            for (int jp = 0; jp < JT / 2; jp++)
                LDSM4(bf[2 * jp][0], bf[2 * jp][1], bf[2 * jp + 1][0], bf[2 * jp + 1][1],
                      bbase + (uint32_t)(jp * 16 * HRS + ks * 16) * 2u);
#pragma unroll
            for (int i = 0; i < 4; i++)
#pragma unroll
                for (int j = 0; j < JT; j++)
                    asm volatile(
                        "mma.sync.aligned.m16n8k16.row.col.f32.f16.f16.f32 "
                        "{%0,%1,%2,%3}, {%4,%5,%6,%7}, {%8,%9}, {%0,%1,%2,%3};"
                        : "+f"(acc[i][j][0]), "+f"(acc[i][j][1]),
                          "+f"(acc[i][j][2]), "+f"(acc[i][j][3])
                        : "r"(af[i][0]), "r"(af[i][1]), "r"(af[i][2]), "r"(af[i][3]),
                          "r"(bf[j][0]), "r"(bf[j][1]));
        }
        if (c + 2 < NC) {
            int nb = buf + 2; if (nb >= HSTAGES) nb -= HSTAGES;
            stage(c + 2, nb);
        }
        if (++buf == HSTAGES) buf = 0;
    }

    // epilogue
#pragma unroll
    for (int i = 0; i < 4; i++) {
        int r0 = bm + wm * 64 + i * 16 + r;
#pragma unroll
        for (int j = 0; j < JT; j++) {
            int c0 = bn + wn * (NT / 4) + j * 8 + cq * 2;
            float v00 = acc[i][j][0], v01 = acc[i][j][1];
            float v10 = acc[i][j][2], v11 = acc[i][j][3];
            if (Res) {
                float2 p0 = *(const float2*)&Res[(size_t)r0 * ldc + c0];
                float2 p1 = *(const float2*)&Res[(size_t)(r0 + 8) * ldc + c0];
                v00 += p0.x; v01 += p0.y;
                v10 += p1.x; v11 += p1.y;
            }
            *(float2*)&C[(size_t)r0 * ldc + c0] = make_float2(v00, v01);
            *(float2*)&C[(size_t)(r0 + 8) * ldc + c0] = make_float2(v10, v11);
        }
    }
}

// ======================================================================================
// tf32 GEMM (scan-feeding path; supports split-K via gridDim.z)
// ======================================================================================
template <int NT>
__global__ __launch_bounds__(256, 1) void gemm_mma(
    const float* __restrict__ A, const float* __restrict__ B,
    float* __restrict__ C, const float* __restrict__ Res, const float* __restrict__ bias,
    int M, int N, int K, int lda, int ldb, int ldc, int act, size_t czstride) {
    constexpr int JT = NT / 32;
    constexpr int SA = 128 * 36;
    constexpr int SB = NT * 36;
    extern __shared__ float smem[];
    float* As = smem;
    float* Bs = smem + 2 * SA;

    {
        int zz = blockIdx.z;
        A += (size_t)zz * K;
        B += (size_t)zz * K;
        C += (size_t)zz * czstride;
    }

    const int tid = threadIdx.x, wid = tid >> 5, lane = tid & 31;
    const int wm = wid >> 2, wn = wid & 3;
    const int bm = blockIdx.x * 128, bn = blockIdx.y * NT;
    const int NC = K >> 5;
    const int r = lane >> 2, cq = lane & 3;
    const int rowin = lane & 7, tsel = lane >> 3;

    float acc[4][JT][4];
#pragma unroll
    for (int i = 0; i < 4; i++)
#pragma unroll
        for (int j = 0; j < JT; j++)
#pragma unroll
            for (int q = 0; q < 4; q++) acc[i][j][q] = 0.f;

    const int srow = tid >> 3, scol = (tid & 7) * 4;

    auto stage = [&](int c, int b) {
        int k0 = c * 32;
        float* sa = As + b * SA;
        float* sb = Bs + b * SB;
#pragma unroll
        for (int i = 0; i < 4; i++) {
            int rr = srow + i * 32;
            cp16(smem_u32(sa + rr * 36 + scol), A + (size_t)(bm + rr) * lda + k0 + scol);
        }
#pragma unroll
        for (int i = 0; i < NT / 32; i++) {
            int rr = srow + i * 32;
            cp16(smem_u32(sb + rr * 36 + scol), B + (size_t)(bn + rr) * ldb + k0 + scol);
        }
        cp_commit();
    };

    const int a_off = (wm * 64 + rowin + (tsel & 1) * 8) * 36 + (tsel >> 1) * 4;
    const int b_off = (wn * (NT / 4) + rowin + (tsel >> 1) * 8) * 36 + (tsel & 1) * 4;

    stage(0, 0);
    for (int c = 0; c < NC; c++) {
        int buf = c & 1;
        if (c + 1 < NC) {
            stage(c + 1, buf ^ 1);
            asm volatile("cp.async.wait_group 1;" ::: "memory");
        } else {
            asm volatile("cp.async.wait_group 0;" ::: "memory");
        }
        __syncthreads();

        const uint32_t abase = smem_u32(As + buf * SA + a_off);
        const uint32_t bbase = smem_u32(Bs + buf * SB + b_off);
#pragma unroll
        for (int ks = 0; ks < 4; ks++) {
            uint32_t af[4][4];
#pragma unroll
            for (int i = 0; i < 4; i++) {
                LDSM4(af[i][0], af[i][1], af[i][2], af[i][3],
                      abase + (uint32_t)(i * 16 * 36 + ks * 8) * 4u);
                af[i][0] = f2tf(af[i][0]); af[i][1] = f2tf(af[i][1]);
                af[i][2] = f2tf(af[i][2]); af[i][3] = f2tf(af[i][3]);
            }
            uint32_t bf[JT][2];
#pragma unroll
            for (int jp = 0; jp < JT / 2; jp++) {
                LDSM4(bf[2 * jp][0], bf[2 * jp][1], bf[2 * jp + 1][0], bf[2 * jp + 1][1],
                      bbase + (uint32_t)(jp * 16 * 36 + ks * 8) * 4u);
                bf[2 * jp][0] = f2tf(bf[2 * jp][0]);
                bf[2 * jp][1] = f2tf(bf[2 * jp][1]);
                bf[2 * jp + 1][0] = f2tf(bf[2 * jp + 1][0]);
                bf[2 * jp + 1][1] = f2tf(bf[2 * jp + 1][1]);
            }
#pragma unroll
            for (int i = 0; i < 4; i++)
#pragma unroll
                for (int j = 0; j < JT; j++)
                    asm volatile(
                        "mma.sync.aligned.m16n8k8.row.col.f32.tf32.tf32.f32 "
                        "{%0,%1,%2,%3}, {%4,%5,%6,%7}, {%8,%9}, {%0,%1,%2,%3};"
                        : "+f"(acc[i][j][0]), "+f"(acc[i][j][1]),
                          "+f"(acc[i][j][2]), "+f"(acc[i][j][3])
                        : "r"(af[i][0]), "r"(af[i][1]), "r"(af[i][2]), "r"(af[i][3]),
                          "r"(bf[j][0]), "r"(bf[j][1]));
        }
        __syncthreads();
    }

#pragma unroll
    for (int i = 0; i < 4; i++) {
        int r0 = bm + wm * 64 + i * 16 + r;
#pragma unroll
        for (int j = 0; j < JT; j++) {
            int c0 = bn + wn * (NT / 4) + j * 8 + cq * 2;
            float v00 = acc[i][j][0], v01 = acc[i][j][1];
            float v10 = acc[i][j][2], v11 = acc[i][j][3];
            if (bias) {
                float b0 = bias[c0], b1 = bias[c0 + 1];
                v00 += b0; v01 += b1; v10 += b0; v11 += b1;
            }
            if (act) {
                v00 = softplus_f(v00); v01 = softplus_f(v01);
                v10 = softplus_f(v10); v11 = softplus_f(v11);
            }
            if (Res) {
                float2 p0 = *(const float2*)&Res[(size_t)r0 * ldc + c0];
                float2 p1 = *(const float2*)&Res[(size_t)(r0 + 8) * ldc + c0];
                v00 += p0.x; v01 += p0.y;
                v10 += p1.x; v11 += p1.y;
            }
            *(float2*)&C[(size_t)r0 * ldc + c0] = make_float2(v00, v01);
            *(float2*)&C[(size_t)(r0 + 8) * ldc + c0] = make_float2(v10, v11);
        }
    }
}

#define SMEM_NT(NT) ((2 * 128 * 36 + 2 * (NT) * 36) * 4)

// ---------------- depthwise causal conv + bias + silu, smem-tiled ----------------
#define CT 32
__global__ __launch_bounds__(256) void conv_silu_kernel(
    const float* __restrict__ xr, const float* __restrict__ cw,
    const float* __restrict__ cb, float* __restrict__ xc) {
    __shared__ float sx[CT + 3][256];
    int d = blockIdx.x * 256 + threadIdx.x;
    int t0 = blockIdx.y * CT;
#pragma unroll 5
    for (int rr = 0; rr < CT + 3; rr++) {
        int ts = t0 - 3 + rr;
        sx[rr][threadIdx.x] = (ts >= 0) ? xr[(size_t)ts * (2 * DI) + d] : 0.f;
    }
    __syncthreads();
    float w0 = cw[d * 4 + 0], w1 = cw[d * 4 + 1], w2 = cw[d * 4 + 2], w3 = cw[d * 4 + 3];
    float bb = cb[d];
#pragma unroll 8
    for (int tt = 0; tt < CT; tt++) {
        float acc = bb;
        acc = fmaf(w0, sx[tt][threadIdx.x], acc);
        acc = fmaf(w1, sx[tt + 1][threadIdx.x], acc);
        acc = fmaf(w2, sx[tt + 2][threadIdx.x], acc);
        acc = fmaf(w3, sx[tt + 3][threadIdx.x], acc);
        xc[(size_t)(t0 + tt) * DI + d] = sigmoid_mul(acc);
    }
}

// ---------------- chunked selective scan ----------------
__global__ __launch_bounds__(128) void scan_phase1(
    const float* __restrict__ delta, const float* __restrict__ u,
    const float* __restrict__ xdbl, const float* __restrict__ A_log,
    float* __restrict__ fin, float* __restrict__ prod) {
    int p = blockIdx.y;
    int d = blockIdx.x * 128 + threadIdx.x;
    __shared__ float Bs[CH][DS];
    for (int i = threadIdx.x; i < CH * DS; i += 128) {
        int tt = i >> 4, n = i & 15;
        Bs[tt][n] = xdbl[(size_t)(p * CH + tt) * XPAD + 48 + n];
    }
    __syncthreads();
    float Aa[DS], x[DS], pa[DS];
#pragma unroll
    for (int n = 0; n < DS; n++) {
        Aa[n] = -__expf(A_log[(size_t)d * DS + n]);
        x[n] = 0.f;
        pa[n] = 1.f;
    }
    for (int tt = 0; tt < CH; tt++) {
        int t = p * CH + tt;
        float dl = delta[(size_t)t * DI + d];
        float uu = u[(size_t)t * DI + d];
        float du = dl * uu;
#pragma unroll
        for (int n = 0; n < DS; n++) {
            float e = __expf(dl * Aa[n]);
            x[n] = fmaf(e, x[n], du * Bs[tt][n]);
            pa[n] *= e;
        }
    }
    size_t base = (size_t)p * DI * DS + (size_t)d * DS;
#pragma unroll
    for (int n = 0; n < DS; n++) { fin[base + n] = x[n]; prod[base + n] = pa[n]; }
}

__global__ void scan_combine(const float* __restrict__ fin, const float* __restrict__ prod,
                             float* __restrict__ init) {
    int i = blockIdx.x * 256 + threadIdx.x;
    if (i >= DI * DS) return;
    float s = 0.f;
#pragma unroll 4
    for (int p = 0; p < NCHUNK; p++) {
        size_t idx = (size_t)p * DI * DS + i;
        init[idx] = s;
        s = fmaf(prod[idx], s, fin[idx]);
    }
}

// phase 2 emits fp16 y directly (only the fp16 out_proj GEMM consumes it)
__global__ __launch_bounds__(128) void scan_phase2(
    const float* __restrict__ delta, const float* __restrict__ u,
    const float* __restrict__ xdbl, const float* __restrict__ A_log,
    const float* __restrict__ init, const float* __restrict__ Dp,
    const float* __restrict__ xr, __half* __restrict__ yout) {
    int p = blockIdx.y;
    int d = blockIdx.x * 128 + threadIdx.x;
    __shared__ float Bs[CH][DS];
    __shared__ float Cs[CH][DS];
    for (int i = threadIdx.x; i < CH * DS; i += 128) {
        int tt = i >> 4, n = i & 15;
        size_t row = (size_t)(p * CH + tt) * XPAD;
        Bs[tt][n] = xdbl[row + 48 + n];
        Cs[tt][n] = xdbl[row + 64 + n];
    }
    __syncthreads();
    float Aa[DS], x[DS];
    size_t base = (size_t)p * DI * DS + (size_t)d * DS;
#pragma unroll
    for (int n = 0; n < DS; n++) {
        Aa[n] = -__expf(A_log[(size_t)d * DS + n]);
        x[n] = init[base + n];
    }
    float Dd = Dp[d];
    for (int tt = 0; tt < CH; tt++) {
        int t = p * CH + tt;
        float dl = delta[(size_t)t * DI + d];
        float uu = u[(size_t)t * DI + d];
        float du = dl * uu;
        float y0 = 0.f, y1 = 0.f, y2 = 0.f, y3 = 0.f;
#pragma unroll
        for (int n = 0; n < DS; n++) {
            float e = __expf(dl * Aa[n]);
            x[n] = fmaf(e, x[n], du * Bs[tt][n]);
            float pr = x[n] * Cs[tt][n];
            if ((n & 3) == 0) y0 += pr;
            else if ((n & 3) == 1) y1 += pr;
            else if ((n & 3) == 2) y2 += pr;
            else y3 += pr;
        }
        float y = (y0 + y1) + (y2 + y3) + uu * Dd;
        float r = xr[(size_t)t * (2 * DI) + DI + d];
        yout[(size_t)t * DI + d] = __float2half(y * sigmoid_mul(r));
    }
}

// ---------------- host orchestration ----------------
template <int NT>
static void launch_mma(const float* A, const float* B, float* C,
                       const float* Res, const float* bias,
                       int M, int N, int K, int lda, int ldb, int ldc, int act,
                       int zsplit = 1, size_t czstride = 0) {
    dim3 grid(M / 128, N / NT, zsplit);
    gemm_mma<NT><<<grid, 256, SMEM_NT(NT)>>>(A, B, C, Res, bias, M, N, K, lda, ldb, ldc,
                                             act, czstride);
}
template <int NT>
static void launch_mma_h(const __half* A, const __half* B, float* C, const float* Res,
                         int M, int N, int K, int lda, int ldb, int ldc,
                         int zsplit = 1, size_t czstride = 0) {
    dim3 grid(M / 128, N / NT, zsplit);
    gemm_mma_h<NT><<<grid, 256, HSMEM_NT(NT)>>>(A, B, C, Res, M, N, K, lda, ldb, ldc, czstride);
}
static void launch_f2h(const float* src, __half* dst, int n) {
    int n4 = n / 4;
    f2h_kernel<<<(n4 + 255) / 256, 256>>>(src, dst, n4);
}

extern "C" void kernel_launch(void* const* d_in, const int* in_sizes, int n_in,
                              void* d_out, int out_size) {
    const int*   tokens = (const int*)d_in[0];
    const float* E      = (const float*)d_in[1];
    const float* in_w   = (const float*)d_in[2];
    const float* conv_w = (const float*)d_in[3];
    const float* conv_b = (const float*)d_in[4];
    const float* xp_w   = (const float*)d_in[5];
    const float* dt_w   = (const float*)d_in[6];
    const float* dt_b   = (const float*)d_in[7];
    const float* A_log  = (const float*)d_in[8];
    const float* Dp     = (const float*)d_in[9];
    const float* out_w  = (const float*)d_in[10];
    const float* nw     = (const float*)d_in[11];
    const float* nb     = (const float*)d_in[12];
    const float* nfw    = (const float*)d_in[13];
    const float* nfb    = (const float*)d_in[14];
    float* logits = (float*)d_out;

    float *h, *xr, *xc, *xdbl, *xdblp, *opart, *delta, *fin, *prod, *init, *xpwp, *dtwp;
    __half *ah, *wh;
    cudaGetSymbolAddress((void**)&h, g_h);
    cudaGetSymbolAddress((void**)&xr, g_xr);
    cudaGetSymbolAddress((void**)&xc, g_xc);
    cudaGetSymbolAddress((void**)&xdbl, g_xdbl);
    cudaGetSymbolAddress((void**)&xdblp, g_xdbl_part);
    cudaGetSymbolAddress((void**)&opart, g_opart);
    cudaGetSymbolAddress((void**)&delta, g_delta);
    cudaGetSymbolAddress((void**)&fin, g_fin);
    cudaGetSymbolAddress((void**)&prod, g_prod);
    cudaGetSymbolAddress((void**)&init, g_init);
    cudaGetSymbolAddress((void**)&xpwp, g_xpw_pad);
    cudaGetSymbolAddress((void**)&dtwp, g_dtw_pad);
    cudaGetSymbolAddress((void**)&ah, g_ah);
    cudaGetSymbolAddress((void**)&wh, g_wh);

    cudaFuncSetAttribute(gemm_mma<256>, cudaFuncAttributeMaxDynamicSharedMemorySize, SMEM_NT(256));
    cudaFuncSetAttribute(gemm_mma<128>, cudaFuncAttributeMaxDynamicSharedMemorySize, SMEM_NT(128));
    cudaFuncSetAttribute(gemm_mma_h<256>, cudaFuncAttributeMaxDynamicSharedMemorySize, HSMEM_NT(256));
    cudaFuncSetAttribute(gemm_mma_h<128>, cudaFuncAttributeMaxDynamicSharedMemorySize, HSMEM_NT(128));

    embed_kernel<<<(L * NE + 255) / 256, 256>>>(tokens, E, h);

    for (int l = 0; l < 2; l++) {
        const float* l_inw  = in_w  + (size_t)l * (2 * DI) * NE;
        const float* l_cw   = conv_w + (size_t)l * DI * 4;
        const float* l_cb   = conv_b + (size_t)l * DI;
        const float* l_xpw  = xp_w  + (size_t)l * 80 * DI;
        const float* l_dtw  = dt_w  + (size_t)l * DI * DTR;
        const float* l_dtb  = dt_b  + (size_t)l * DI;
        const float* l_alog = A_log + (size_t)l * DI * DS;
        const float* l_dp   = Dp    + (size_t)l * DI;
        const float* l_outw = out_w + (size_t)l * NE * DI;

        pad_xpw_kernel<<<(128 * DI + 255) / 256, 256>>>(l_xpw, xpwp);
        pad_dtw_kernel<<<(DI * 64 + 255) / 256, 256>>>(l_dtw, dtwp);

        // ah = fp16 rmsnorm(h)
        rmsnorm_h_kernel<<<L, 256>>>(h, nw + l * NE, nb + l * NE, ah);
        // xr = ah @ in_proj^T  [L, 3072]  (fp16, NT=128 for grid balance, BK=64)
        launch_f2h(l_inw, wh, 2 * DI * NE);
        launch_mma_h<128>(ah, wh, xr, nullptr, L, 2 * DI, NE, NE, NE, 2 * DI);
        // xc = silu(depthwise causal conv(x) + b)   (smem-tiled)
        conv_silu_kernel<<<dim3(DI / 256, L / CT), 256>>>(xr, l_cw, l_cb, xc);
        // xdbl = xc @ xpw_pad^T  [L, 128]  (tf32, split-K x8 + deterministic reduce)
        launch_mma<128>(xc, xpwp, xdblp, nullptr, nullptr, L, XPAD, DI / KSPL,
                        DI, DI, XPAD, 0, KSPL, (size_t)L * XPAD);
        reduce_k_kernel<<<(L * XPAD + 255) / 256, 256>>>(xdblp, xdbl, L * XPAD);
        // delta = softplus(xdbl[:, :64] @ dtw_pad^T + dt_b)  [L, 1536]  (tf32)
        launch_mma<256>(xdbl, dtwp, delta, nullptr, l_dtb, L, DI, 64, XPAD, 64, DI, 1);
        // chunked selective scan -> y (fp16, written to ah)
        scan_phase1<<<dim3(DI / 128, NCHUNK), 128>>>(delta, xc, xdbl, l_alog, fin, prod);
        scan_combine<<<(DI * DS + 255) / 256, 256>>>(fin, prod, init);
        scan_phase2<<<dim3(DI / 128, NCHUNK), 128>>>(delta, xc, xdbl, l_alog, init, l_dp, xr, ah);
        // h = h + y @ out_proj^T  (fp16, NT=128 split-K x4 + fused residual reduce, BK=64)
        launch_f2h(l_outw, wh, NE * DI);
        launch_mma_h<128>(ah, wh, opart, nullptr, L, NE, DI / KSPO, DI, DI, NE,
                          KSPO, (size_t)L * NE);
        reduce_res_kernel<<<(L * NE / 4 + 255) / 256, 256>>>(opart, h, L * NE / 4);
    }

    // final norm + tied lm head (fp16, NT=256, BK=64)
    rmsnorm_h_kernel<<<L, 256>>>(h, nfw, nfb, ah);
    launch_f2h(E, wh, 32000 * NE);
    launch_mma_h<256>(ah, wh, logits, nullptr, L, 32000, NE, NE, NE, 32000);
}